// round 2
// baseline (speedup 1.0000x reference)
#include <cuda_runtime.h>
#include <math.h>

#define BB   2
#define SS   512
#define DM   768
#define HH   12
#define DH   64
#define EA   4
#define EF   8
#define DFF  3072
#define NTOK (BB*SS)
#define CAP  160
#define NE   (NTOK*2)

__device__ float g_xln1[NTOK*DM];
__device__ float g_q[NTOK*DM];
__device__ float g_k[NTOK*DM];
__device__ float g_r[NTOK*HH*EA];
__device__ int   g_idx[NTOK*HH];
__device__ int   g_hard[HH*EA];
__device__ float g_vproj[HH*NTOK*DH];
__device__ float g_p[HH*BB*SS*SS];
__device__ float g_ao[HH*NTOK*DH];
__device__ float g_x1[NTOK*DM];
__device__ float g_xln2[NTOK*DM];
__device__ float g_gl[NTOK*EF];
__device__ int   g_ee[NE];
__device__ int   g_epos[NE];
__device__ float g_ew[NE];
__device__ int   g_ekeep[NE];
__device__ float g_buf[EF*CAP*DM];
__device__ float g_hmid[EF*CAP*DFF];
__device__ float g_ybuf[EF*CAP*DM];
__device__ float g_ybuf2[EF*CAP*DM];
__device__ float g_aux[2];

// ---------------------------------------------------------------------------
// LayerNorm
// ---------------------------------------------------------------------------
__global__ __launch_bounds__(256) void ln_kernel(const float* __restrict__ x,
                                                 const float* __restrict__ g,
                                                 const float* __restrict__ b,
                                                 float* __restrict__ out)
{
    int n = blockIdx.x;
    const float* row = x + (size_t)n * DM;
    float s = 0.f, ss = 0.f;
    for (int d = threadIdx.x; d < DM; d += 256) {
        float v = row[d];
        s += v; ss += v * v;
    }
    __shared__ float shs[8], shq[8];
    int lane = threadIdx.x & 31, wid = threadIdx.x >> 5;
    #pragma unroll
    for (int o = 16; o; o >>= 1) { s += __shfl_xor_sync(~0u, s, o); ss += __shfl_xor_sync(~0u, ss, o); }
    if (lane == 0) { shs[wid] = s; shq[wid] = ss; }
    __syncthreads();
    if (threadIdx.x == 0) {
        float ts = 0, tq = 0;
        for (int i = 0; i < 8; i++) { ts += shs[i]; tq += shq[i]; }
        shs[0] = ts; shq[0] = tq;
    }
    __syncthreads();
    float mu = shs[0] / DM;
    float var = shq[0] / DM - mu * mu;
    float inv = rsqrtf(var + 1e-5f);
    for (int d = threadIdx.x; d < DM; d += 256)
        out[(size_t)n * DM + d] = (row[d] - mu) * inv * g[d] + b[d];
}

// ---------------------------------------------------------------------------
// 128x128x8 double-buffered SGEMM, 8x8 micro-tile (quadrant layout).
// TA: 0 = A row-major [m,lda], 1 = A K-major [k*lda + m]
// TB: 0 = B row-major [k*ldb + n], 1 = B N-major [n*ldb + k] (i.e. B^T)
// LAYOUT: 0 = z-strided batch, 1 = dual (z selects B0/C0 vs B1/C1),
//         2 = attention scores (z = h*BB+b; head-slice offsets),
//         3 = split-K expert batch (z = e*2+half; half selects C0/C1)
// ---------------------------------------------------------------------------
__device__ __forceinline__ float4 zero4() { return make_float4(0.f, 0.f, 0.f, 0.f); }

template<int TA, int TB, int RELU, int LAYOUT>
__global__ __launch_bounds__(256, 2) void gemm128(
    const float* __restrict__ A, const float* __restrict__ B0,
    const float* __restrict__ B1, float* __restrict__ C0, float* __restrict__ C1,
    int M, int N, int K, int lda, int ldb, int ldc,
    size_t sA, size_t sB, size_t sC)
{
    const float* Ap = A;
    const float* Bp = B0;
    float* Cp = C0;
    int z = blockIdx.z;
    if (LAYOUT == 0) {
        Ap += (size_t)z * sA; Bp += (size_t)z * sB; Cp += (size_t)z * sC;
    } else if (LAYOUT == 1) {
        Bp = z ? B1 : B0; Cp = z ? C1 : C0;
    } else if (LAYOUT == 2) {
        int b = z & 1, h = z >> 1;
        Ap += (size_t)(b * SS) * lda + (size_t)h * DH;
        Bp += (size_t)(b * SS) * ldb + (size_t)h * DH;
        Cp += (size_t)z * SS * SS;
    } else { // 3
        int e = z >> 1, hf = z & 1;
        Ap += (size_t)e * sA + (size_t)hf * K;
        Bp += (size_t)e * sB + (size_t)hf * K * ldb;
        Cp = (hf ? C1 : C0) + (size_t)e * sC;
    }

    int m0 = blockIdx.y * 128, n0 = blockIdx.x * 128;
    int tid = threadIdx.x;
    int tx = tid & 15, ty = tid >> 4;

    __shared__ float As[2][8][132];
    __shared__ float Bs[2][8][132];

    auto loadA = [&](int k0) -> float4 {
        if (TA == 0) {
            int row = tid >> 1, kc = (tid & 1) * 4;
            int m = m0 + row;
            return (m < M) ? *(const float4*)(Ap + (size_t)m * lda + k0 + kc) : zero4();
        } else {
            int kk = tid >> 5, m4 = (tid & 31) * 4;
            int m = m0 + m4;
            return (m < M) ? *(const float4*)(Ap + (size_t)(k0 + kk) * lda + m) : zero4();
        }
    };
    auto storeA = [&](float4 v, int buf) {
        if (TA == 0) {
            int row = tid >> 1, kc = (tid & 1) * 4;
            As[buf][kc + 0][row] = v.x; As[buf][kc + 1][row] = v.y;
            As[buf][kc + 2][row] = v.z; As[buf][kc + 3][row] = v.w;
        } else {
            int kk = tid >> 5, m4 = (tid & 31) * 4;
            *(float4*)&As[buf][kk][m4] = v;
        }
    };
    auto loadB = [&](int k0) -> float4 {
        if (TB == 0) {
            int kk = tid >> 5, n4 = (tid & 31) * 4;
            int n = n0 + n4;
            return (n < N) ? *(const float4*)(Bp + (size_t)(k0 + kk) * ldb + n) : zero4();
        } else {
            int nr = tid >> 1, kc = (tid & 1) * 4;
            int n = n0 + nr;
            return (n < N) ? *(const float4*)(Bp + (size_t)n * ldb + k0 + kc) : zero4();
        }
    };
    auto storeB = [&](float4 v, int buf) {
        if (TB == 0) {
            int kk = tid >> 5, n4 = (tid & 31) * 4;
            *(float4*)&Bs[buf][kk][n4] = v;
        } else {
            int nr = tid >> 1, kc = (tid & 1) * 4;
            Bs[buf][kc + 0][nr] = v.x; Bs[buf][kc + 1][nr] = v.y;
            Bs[buf][kc + 2][nr] = v.z; Bs[buf][kc + 3][nr] = v.w;
        }
    };

    float acc[8][8] = {};

    storeA(loadA(0), 0);
    storeB(loadB(0), 0);
    __syncthreads();

    int nk = K >> 3;
    for (int t = 0; t < nk; t++) {
        int cur = t & 1;
        float4 pa, pb;
        bool has = (t + 1 < nk);
        if (has) { pa = loadA((t + 1) * 8); pb = loadB((t + 1) * 8); }
        #pragma unroll
        for (int k = 0; k < 8; k++) {
            float4 a0 = *(const float4*)&As[cur][k][ty * 4];
            float4 a1 = *(const float4*)&As[cur][k][64 + ty * 4];
            float4 b0 = *(const float4*)&Bs[cur][k][tx * 4];
            float4 b1 = *(const float4*)&Bs[cur][k][64 + tx * 4];
            float av[8] = {a0.x, a0.y, a0.z, a0.w, a1.x, a1.y, a1.z, a1.w};
            float bv[8] = {b0.x, b0.y, b0.z, b0.w, b1.x, b1.y, b1.z, b1.w};
            #pragma unroll
            for (int i = 0; i < 8; i++)
                #pragma unroll
                for (int j = 0; j < 8; j++)
                    acc[i][j] += av[i] * bv[j];
        }
        if (has) { storeA(pa, cur ^ 1); storeB(pb, cur ^ 1); }
        __syncthreads();
    }

    #pragma unroll
    for (int i = 0; i < 8; i++) {
        int m = m0 + ((i < 4) ? (ty * 4 + i) : (64 + ty * 4 + i - 4));
        if (m >= M) continue;
        #pragma unroll
        for (int jh = 0; jh < 2; jh++) {
            int n = n0 + (jh ? (64 + tx * 4) : (tx * 4));
            if (n >= N) continue;
            float4 v;
            v.x = acc[i][jh * 4 + 0]; v.y = acc[i][jh * 4 + 1];
            v.z = acc[i][jh * 4 + 2]; v.w = acc[i][jh * 4 + 3];
            if (RELU) {
                v.x = fmaxf(v.x, 0.f); v.y = fmaxf(v.y, 0.f);
                v.z = fmaxf(v.z, 0.f); v.w = fmaxf(v.w, 0.f);
            }
            *(float4*)(Cp + (size_t)m * ldc + n) = v;
        }
    }
}

// ---------------------------------------------------------------------------
// routing / small kernels
// ---------------------------------------------------------------------------
__global__ void init_hard_kernel()
{
    if (threadIdx.x < HH * EA) g_hard[threadIdx.x] = 0;
}

__global__ void argmax_kernel()
{
    int i = blockIdx.x * blockDim.x + threadIdx.x;
    if (i >= NTOK * HH) return;
    int n = i / HH, h = i % HH;
    const float* g = g_r + (size_t)n * (HH * EA) + h * EA;
    int best = 0; float bv = g[0];
    #pragma unroll
    for (int a = 1; a < EA; a++) if (g[a] > bv) { bv = g[a]; best = a; }
    g_idx[i] = best;
    atomicAdd(&g_hard[h * EA + best], 1);
}

__global__ void aux1_kernel()
{
    if (threadIdx.x != 0) return;
    float e[HH * EA];
    float tot = 0.f;
    for (int i = 0; i < HH * EA; i++) { e[i] = 0.01f * (float)g_hard[i] / (float)NTOK; tot += e[i]; }
    float a = 0.f;
    for (int i = 0; i < HH * EA; i++) { float pr = e[i] / (tot + 1e-9f); a += pr * pr; }
    g_aux[0] = a * (float)(EA * HH);
}

__global__ __launch_bounds__(64) void vproj_kernel(const float* __restrict__ Wv)
{
    int n = blockIdx.x, h = blockIdx.y, e = threadIdx.x;
    __shared__ float xs[DH];
    xs[e] = g_xln1[(size_t)n * DM + h * DH + e];
    __syncthreads();
    int a = g_idx[n * HH + h];
    const float* W = Wv + ((size_t)(h * EA + a)) * DH * DH;
    float acc = 0.f;
    #pragma unroll
    for (int d = 0; d < DH; d++) acc += xs[d] * W[d * DH + e];
    g_vproj[((size_t)h * NTOK + n) * DH + e] = acc;
}

__global__ __launch_bounds__(64) void oproj_kernel(const float* __restrict__ Wo,
                                                   const float* __restrict__ xres)
{
    int n = blockIdx.x, h = blockIdx.y, e = threadIdx.x;
    __shared__ float xs[DH];
    xs[e] = g_ao[((size_t)h * NTOK + n) * DH + e];
    __syncthreads();
    int a = g_idx[n * HH + h];
    const float* W = Wo + ((size_t)(h * EA + a)) * DH * DH;
    float acc = 0.f;
    #pragma unroll
    for (int d = 0; d < DH; d++) acc += xs[d] * W[d * DH + e];
    size_t off = (size_t)n * DM + h * DH + e;
    g_x1[off] = xres[off] + acc;
}

// softmax over rows of g_p with scale + causal mask
__global__ __launch_bounds__(256) void softmax_kernel(const float* __restrict__ mask)
{
    int row = blockIdx.x;               // bh*SS + s
    int tid = threadIdx.x;
    int s = row & (SS - 1);
    float* p = g_p + (size_t)row * SS;
    const float* mr = mask + (size_t)s * SS;

    float v0 = p[tid] * 0.125f + mr[tid];
    float v1 = p[tid + 256] * 0.125f + mr[tid + 256];

    __shared__ float red[8];
    int lane = tid & 31, w = tid >> 5;

    float mx = fmaxf(v0, v1);
    #pragma unroll
    for (int o = 16; o; o >>= 1) mx = fmaxf(mx, __shfl_xor_sync(~0u, mx, o));
    if (lane == 0) red[w] = mx;
    __syncthreads();
    if (w == 0) {
        float m = (lane < 8) ? red[lane] : -1e30f;
        #pragma unroll
        for (int o = 4; o; o >>= 1) m = fmaxf(m, __shfl_xor_sync(~0u, m, o));
        if (lane == 0) red[0] = m;
    }
    __syncthreads();
    mx = red[0];
    __syncthreads();

    float e0 = expf(v0 - mx), e1 = expf(v1 - mx);
    float sm = e0 + e1;
    #pragma unroll
    for (int o = 16; o; o >>= 1) sm += __shfl_xor_sync(~0u, sm, o);
    if (lane == 0) red[w] = sm;
    __syncthreads();
    if (w == 0) {
        float m = (lane < 8) ? red[lane] : 0.f;
        #pragma unroll
        for (int o = 4; o; o >>= 1) m += __shfl_xor_sync(~0u, m, o);
        if (lane == 0) red[0] = m;
    }
    __syncthreads();
    float inv = 1.f / red[0];
    p[tid] = e0 * inv;
    p[tid + 256] = e1 * inv;
}

__global__ __launch_bounds__(256) void route_kernel()
{
    int tid = threadIdx.x;
    __shared__ int   s_e[NE];
    __shared__ float s_p[NE];
    __shared__ int   s_pos[NE];
    __shared__ int   s_keep[NE];
    __shared__ float s_imp[EF];
    __shared__ int   s_cnt[EF];

    for (int n = tid; n < NTOK; n += 256) {
        const float* g = g_gl + (size_t)n * EF;
        int i0 = 0; float v0 = g[0];
        #pragma unroll
        for (int j = 1; j < EF; j++) if (g[j] > v0) { v0 = g[j]; i0 = j; }
        int i1 = -1; float v1 = -1e30f;
        #pragma unroll
        for (int j = 0; j < EF; j++) { if (j == i0) continue; if (g[j] > v1) { v1 = g[j]; i1 = j; } }
        float e1 = expf(v1 - v0);
        float den = 1.f + e1;
        s_e[2 * n] = i0; s_e[2 * n + 1] = i1;
        s_p[2 * n] = 1.f / den; s_p[2 * n + 1] = e1 / den;
    }
    __syncthreads();
    if (tid == 0) {
        int cnt[EF] = {};
        for (int j = 0; j < NE; j++) {
            int e = s_e[j];
            int p = cnt[e]++;
            s_pos[j] = p;
            s_keep[j] = (p < CAP) ? 1 : 0;
        }
    }
    __syncthreads();
    if (tid < EF) { s_imp[tid] = 0.f; s_cnt[tid] = 0; }
    __syncthreads();
    for (int n = tid; n < NTOK; n += 256) {
        float p0 = s_p[2 * n]     * (float)s_keep[2 * n];
        float p1 = s_p[2 * n + 1] * (float)s_keep[2 * n + 1];
        float den = p0 + p1 + 1e-9f;
        float w0 = p0 / den, w1 = p1 / den;
        g_ew[2 * n] = w0;      g_ew[2 * n + 1] = w1;
        g_ee[2 * n] = s_e[2 * n];       g_ee[2 * n + 1] = s_e[2 * n + 1];
        g_epos[2 * n] = s_pos[2 * n];   g_epos[2 * n + 1] = s_pos[2 * n + 1];
        g_ekeep[2 * n] = s_keep[2 * n]; g_ekeep[2 * n + 1] = s_keep[2 * n + 1];
        if (s_keep[2 * n])     { atomicAdd(&s_cnt[s_e[2 * n]], 1);     atomicAdd(&s_imp[s_e[2 * n]], w0); }
        if (s_keep[2 * n + 1]) { atomicAdd(&s_cnt[s_e[2 * n + 1]], 1); atomicAdd(&s_imp[s_e[2 * n + 1]], w1); }
    }
    __syncthreads();
    if (tid == 0) {
        float ct = 0.f, it = 0.f;
        for (int e = 0; e < EF; e++) { ct += (float)s_cnt[e]; it += s_imp[e]; }
        float a = 0.f;
        for (int e = 0; e < EF; e++)
            a += ((float)s_cnt[e] / (ct + 1e-9f)) * (s_imp[e] / (it + 1e-9f));
        g_aux[1] = a * (float)EF;
    }
}

__global__ __launch_bounds__(192) void scatter_kernel()
{
    int j = blockIdx.x;
    if (!g_ekeep[j]) return;
    int tok = j >> 1;
    float4* dst = (float4*)(g_buf + ((size_t)g_ee[j] * CAP + g_epos[j]) * DM);
    const float4* src = (const float4*)(g_xln2 + (size_t)tok * DM);
    for (int d = threadIdx.x; d < DM / 4; d += 192) dst[d] = src[d];
}

__global__ __launch_bounds__(256) void output_kernel(float* __restrict__ out, int out_size)
{
    int n = blockIdx.x, tid = threadIdx.x;
    float w0 = g_ew[2 * n], w1 = g_ew[2 * n + 1];
    size_t o0 = ((size_t)g_ee[2 * n]     * CAP + g_epos[2 * n])     * DM;
    size_t o1 = ((size_t)g_ee[2 * n + 1] * CAP + g_epos[2 * n + 1]) * DM;
    bool k0 = g_ekeep[2 * n] != 0, k1 = g_ekeep[2 * n + 1] != 0;
    for (int d = tid; d < DM; d += 256) {
        float f = 0.f;
        if (k0) f += w0 * (g_ybuf[o0 + d] + g_ybuf2[o0 + d]);
        if (k1) f += w1 * (g_ybuf[o1 + d] + g_ybuf2[o1 + d]);
        out[(size_t)n * DM + d] = g_x1[(size_t)n * DM + d] + f;
    }
    if (n == 0 && tid == 0 && out_size > NTOK * DM)
        out[NTOK * DM] = g_aux[0] + g_aux[1];
}

// ---------------------------------------------------------------------------
// host launcher
// ---------------------------------------------------------------------------
extern "C" void kernel_launch(void* const* d_in, const int* in_sizes, int n_in,
                              void* d_out, int out_size)
{
    const float* x        = (const float*)d_in[0];
    const float* mask     = (const float*)d_in[1];
    const float* ln1_g    = (const float*)d_in[2];
    const float* ln1_b    = (const float*)d_in[3];
    const float* ln2_g    = (const float*)d_in[4];
    const float* ln2_b    = (const float*)d_in[5];
    const float* W_q      = (const float*)d_in[6];
    const float* W_k      = (const float*)d_in[7];
    const float* W_v      = (const float*)d_in[8];
    const float* W_o      = (const float*)d_in[9];
    const float* router_w = (const float*)d_in[10];
    const float* gate_w   = (const float*)d_in[11];
    const float* W1       = (const float*)d_in[12];
    const float* W2       = (const float*)d_in[13];
    float* out = (float*)d_out;

    float *p_xln1, *p_q, *p_k, *p_r, *p_p, *p_vproj, *p_ao, *p_x1, *p_xln2,
          *p_gl, *p_buf, *p_hmid, *p_ybuf, *p_ybuf2;
    cudaGetSymbolAddress((void**)&p_xln1,  g_xln1);
    cudaGetSymbolAddress((void**)&p_q,     g_q);
    cudaGetSymbolAddress((void**)&p_k,     g_k);
    cudaGetSymbolAddress((void**)&p_r,     g_r);
    cudaGetSymbolAddress((void**)&p_p,     g_p);
    cudaGetSymbolAddress((void**)&p_vproj, g_vproj);
    cudaGetSymbolAddress((void**)&p_ao,    g_ao);
    cudaGetSymbolAddress((void**)&p_x1,    g_x1);
    cudaGetSymbolAddress((void**)&p_xln2,  g_xln2);
    cudaGetSymbolAddress((void**)&p_gl,    g_gl);
    cudaGetSymbolAddress((void**)&p_buf,   g_buf);
    cudaGetSymbolAddress((void**)&p_hmid,  g_hmid);
    cudaGetSymbolAddress((void**)&p_ybuf,  g_ybuf);
    cudaGetSymbolAddress((void**)&p_ybuf2, g_ybuf2);

    init_hard_kernel<<<1, 64>>>();
    ln_kernel<<<NTOK, 256>>>(x, ln1_g, ln1_b, p_xln1);

    // Q and K fused in one launch (z selects weight/output)
    gemm128<0,0,0,1><<<dim3(6, 8, 2), 256>>>(p_xln1, W_q, W_k, p_q, p_k,
                                             NTOK, DM, DM, DM, DM, DM, 0, 0, 0);
    // router logits
    gemm128<0,0,0,0><<<dim3(1, 8, 1), 256>>>(p_xln1, router_w, nullptr, p_r, nullptr,
                                             NTOK, HH*EA, DM, DM, HH*EA, HH*EA, 0, 0, 0);

    argmax_kernel<<<(NTOK*HH + 255)/256, 256>>>();
    aux1_kernel<<<1, 32>>>();

    vproj_kernel<<<dim3(NTOK, HH), 64>>>(W_v);

    // raw scores = Q K^T  (per b,h)
    gemm128<0,1,0,2><<<dim3(4, 4, HH*BB), 256>>>(p_q, p_k, nullptr, p_p, nullptr,
                                                 SS, SS, DH, DM, DM, SS, 0, 0, 0);
    softmax_kernel<<<HH*BB*SS, 256>>>(mask);

    // attn_out = P^T @ V (contracts query dim, per reference einsum)
    gemm128<1,0,0,0><<<dim3(1, 4, HH*BB), 256>>>(p_p, p_vproj, nullptr, p_ao, nullptr,
                                                 SS, DH, SS, SS, DH, DH,
                                                 (size_t)SS*SS, (size_t)SS*DH, (size_t)SS*DH);

    oproj_kernel<<<dim3(NTOK, HH), 64>>>(W_o, x);

    ln_kernel<<<NTOK, 256>>>(p_x1, ln2_g, ln2_b, p_xln2);
    gemm128<0,0,0,0><<<dim3(1, 8, 1), 256>>>(p_xln2, gate_w, nullptr, p_gl, nullptr,
                                             NTOK, EF, DM, DM, EF, EF, 0, 0, 0);

    route_kernel<<<1, 256>>>();
    scatter_kernel<<<NE, 192>>>();

    // expert FF1 (relu)
    gemm128<0,0,1,0><<<dim3(24, 2, EF), 256>>>(p_buf, W1, nullptr, p_hmid, nullptr,
                                               CAP, DFF, DM, DM, DFF, DFF,
                                               (size_t)CAP*DM, (size_t)DM*DFF, (size_t)CAP*DFF);
    // expert FF2 split-K=2 (z = e*2+half), partials in ybuf/ybuf2
    gemm128<0,0,0,3><<<dim3(6, 2, EF*2), 256>>>(p_hmid, W2, nullptr, p_ybuf, p_ybuf2,
                                                CAP, DM, DFF/2, DFF, DM, DM,
                                                (size_t)CAP*DFF, (size_t)DFF*DM, (size_t)CAP*DM);

    output_kernel<<<NTOK, 256>>>(out, out_size);
}

// round 3
// speedup vs baseline: 1.6019x; 1.6019x over previous
#include <cuda_runtime.h>
#include <math.h>

#define BB   2
#define SS   512
#define DM   768
#define HH   12
#define DH   64
#define EA   4
#define EF   8
#define DFF  3072
#define NTOK (BB*SS)
#define CAP  160
#define NE   (NTOK*2)
#define PSPLIT ((size_t)EF*CAP*DM)

__device__ float g_xln1[NTOK*DM];
__device__ float g_qk[2*NTOK*DM];
__device__ float g_r[NTOK*HH*EA];
__device__ int   g_idx[NTOK*HH];
__device__ int   g_hard[HH*EA];
__device__ float g_vproj[HH*NTOK*DH];
__device__ float g_p[HH*BB*SS*SS];
__device__ float g_ao[HH*NTOK*DH];
__device__ float g_x1[NTOK*DM];
__device__ float g_xln2[NTOK*DM];
__device__ float g_gl[NTOK*EF];
__device__ int   g_ee[NE];
__device__ int   g_epos[NE];
__device__ float g_ew[NE];
__device__ int   g_ekeep[NE];
__device__ float g_buf[EF*CAP*DM];
__device__ float g_hmid[EF*CAP*DFF];
__device__ float g_ybuf[4*EF*CAP*DM];
__device__ float g_aux[2];

__device__ __forceinline__ unsigned long long pk2(float lo, float hi) {
    unsigned long long r;
    asm("mov.b64 %0, {%1,%2};" : "=l"(r) : "f"(lo), "f"(hi));
    return r;
}
__device__ __forceinline__ void upk2(unsigned long long v, float& lo, float& hi) {
    asm("mov.b64 {%0,%1}, %2;" : "=f"(lo), "=f"(hi) : "l"(v));
}
__device__ __forceinline__ void fma2(unsigned long long& d, unsigned long long a,
                                     unsigned long long b) {
    asm("fma.rn.f32x2 %0, %1, %2, %0;" : "+l"(d) : "l"(a), "l"(b));
}

__global__ __launch_bounds__(256) void ln_kernel(const float* __restrict__ x,
                                                 const float* __restrict__ g,
                                                 const float* __restrict__ b,
                                                 float* __restrict__ out)
{
    int n = blockIdx.x;
    const float* row = x + (size_t)n * DM;
    float s = 0.f, ss = 0.f;
    for (int d = threadIdx.x; d < DM; d += 256) {
        float v = row[d];
        s += v; ss += v * v;
    }
    __shared__ float shs[8], shq[8];
    int lane = threadIdx.x & 31, wid = threadIdx.x >> 5;
    #pragma unroll
    for (int o = 16; o; o >>= 1) { s += __shfl_xor_sync(~0u, s, o); ss += __shfl_xor_sync(~0u, ss, o); }
    if (lane == 0) { shs[wid] = s; shq[wid] = ss; }
    __syncthreads();
    if (threadIdx.x == 0) {
        float ts = 0, tq = 0;
        for (int i = 0; i < 8; i++) { ts += shs[i]; tq += shq[i]; }
        shs[0] = ts; shq[0] = tq;
    }
    __syncthreads();
    float mu = shs[0] / DM;
    float var = shq[0] / DM - mu * mu;
    float inv = rsqrtf(var + 1e-5f);
    for (int d = threadIdx.x; d < DM; d += 256)
        out[(size_t)n * DM + d] = (row[d] - mu) * inv * g[d] + b[d];
}

template<int TM, int TN, int TA, int TB, int RELU, int LAYOUT, int TRI>
__global__ __launch_bounds__(64) void gemm_t(
    const float* __restrict__ A, const float* __restrict__ B0,
    const float* __restrict__ B1, float* __restrict__ C,
    int M, int N, int K, int lda, int ldb, int ldc,
    size_t sA, size_t sB, size_t sC)
{
    const float* Ap = A;
    const float* Bp = B0;
    float* Cp = C;
    int z = blockIdx.z;
    if (LAYOUT == 0) {
        Ap += (size_t)z * sA; Bp += (size_t)z * sB; Cp += (size_t)z * sC;
    } else if (LAYOUT == 1) {
        Bp = z ? B1 : B0; Cp += (size_t)z * sC;
    } else if (LAYOUT == 2) {
        int b = z & 1, h = z >> 1;
        Ap += (size_t)(b * SS) * lda + (size_t)h * DH;
        Bp += (size_t)(b * SS) * ldb + (size_t)h * DH;
        Cp += (size_t)z * SS * SS;
    } else {
        int e = z >> 2, part = z & 3;
        Ap += (size_t)e * sA + (size_t)part * K;
        Bp += (size_t)e * sB + (size_t)part * K * ldb;
        Cp += (size_t)part * PSPLIT + (size_t)e * sC;
    }

    int m0 = blockIdx.y * TM, n0 = blockIdx.x * TN;
    if (TRI == 1 && n0 >= m0 + TM) return;

    int tid = threadIdx.x;
    constexpr int TX = TN / 8;
    int ty = tid / TX, tx = tid % TX;

    __shared__ float As[2][8][TM + 4];
    __shared__ float Bs[2][8][TN + 4];

    constexpr int AIT = (2 * TM) / 64;
    constexpr int BIT = (2 * TN) / 64;

    float4 pa[AIT], pb[BIT];

    auto loadA = [&](int k0) {
        #pragma unroll
        for (int r = 0; r < AIT; r++) {
            int idx = tid + r * 64;
            if (TA == 0) {
                int row = idx >> 1, kh = (idx & 1) * 4;
                pa[r] = *(const float4*)(Ap + (size_t)(m0 + row) * lda + k0 + kh);
            } else {
                int k = idx / (TM / 4), m4 = (idx % (TM / 4)) * 4;
                pa[r] = *(const float4*)(Ap + (size_t)(k0 + k) * lda + m0 + m4);
            }
        }
    };
    auto storeA = [&](int buf) {
        #pragma unroll
        for (int r = 0; r < AIT; r++) {
            int idx = tid + r * 64;
            if (TA == 0) {
                int row = idx >> 1, kh = (idx & 1) * 4;
                As[buf][kh + 0][row] = pa[r].x; As[buf][kh + 1][row] = pa[r].y;
                As[buf][kh + 2][row] = pa[r].z; As[buf][kh + 3][row] = pa[r].w;
            } else {
                int k = idx / (TM / 4), m4 = (idx % (TM / 4)) * 4;
                *(float4*)&As[buf][k][m4] = pa[r];
            }
        }
    };
    auto loadB = [&](int k0) {
        #pragma unroll
        for (int r = 0; r < BIT; r++) {
            int idx = tid + r * 64;
            if (TB == 0) {
                int k = idx / (TN / 4), n4 = (idx % (TN / 4)) * 4;
                pb[r] = *(const float4*)(Bp + (size_t)(k0 + k) * ldb + n0 + n4);
            } else {
                int n = idx >> 1, kh = (idx & 1) * 4;
                pb[r] = *(const float4*)(Bp + (size_t)(n0 + n) * ldb + k0 + kh);
            }
        }
    };
    auto storeB = [&](int buf) {
        #pragma unroll
        for (int r = 0; r < BIT; r++) {
            int idx = tid + r * 64;
            if (TB == 0) {
                int k = idx / (TN / 4), n4 = (idx % (TN / 4)) * 4;
                *(float4*)&Bs[buf][k][n4] = pb[r];
            } else {
                int n = idx >> 1, kh = (idx & 1) * 4;
                Bs[buf][kh + 0][n] = pb[r].x; Bs[buf][kh + 1][n] = pb[r].y;
                Bs[buf][kh + 2][n] = pb[r].z; Bs[buf][kh + 3][n] = pb[r].w;
            }
        }
    };

    unsigned long long acc[8][4];
    #pragma unroll
    for (int i = 0; i < 8; i++)
        #pragma unroll
        for (int j = 0; j < 4; j++) acc[i][j] = 0ull;

    int kbeg = (TRI == 2) ? m0 : 0;
    int nk = (K - kbeg) >> 3;

    loadA(kbeg); storeA(0);
    loadB(kbeg); storeB(0);
    __syncthreads();

    for (int t = 0; t < nk; t++) {
        int cur = t & 1;
        bool has = (t + 1 < nk);
        if (has) { loadA(kbeg + (t + 1) * 8); loadB(kbeg + (t + 1) * 8); }
        #pragma unroll
        for (int k = 0; k < 8; k++) {
            float4 a0 = *(const float4*)&As[cur][k][ty * 8];
            float4 a1 = *(const float4*)&As[cur][k][ty * 8 + 4];
            float4 b0 = *(const float4*)&Bs[cur][k][tx * 8];
            float4 b1 = *(const float4*)&Bs[cur][k][tx * 8 + 4];
            unsigned long long bp[4] = {pk2(b0.x, b0.y), pk2(b0.z, b0.w),
                                        pk2(b1.x, b1.y), pk2(b1.z, b1.w)};
            float av[8] = {a0.x, a0.y, a0.z, a0.w, a1.x, a1.y, a1.z, a1.w};
            #pragma unroll
            for (int i = 0; i < 8; i++) {
                unsigned long long ap = pk2(av[i], av[i]);
                #pragma unroll
                for (int j = 0; j < 4; j++) fma2(acc[i][j], ap, bp[j]);
            }
        }
        if (has) { storeA(cur ^ 1); storeB(cur ^ 1); }
        __syncthreads();
    }

    #pragma unroll
    for (int i = 0; i < 8; i++) {
        int m = m0 + ty * 8 + i;
        float4 v0, v1;
        upk2(acc[i][0], v0.x, v0.y); upk2(acc[i][1], v0.z, v0.w);
        upk2(acc[i][2], v1.x, v1.y); upk2(acc[i][3], v1.z, v1.w);
        if (RELU) {
            v0.x = fmaxf(v0.x, 0.f); v0.y = fmaxf(v0.y, 0.f);
            v0.z = fmaxf(v0.z, 0.f); v0.w = fmaxf(v0.w, 0.f);
            v1.x = fmaxf(v1.x, 0.f); v1.y = fmaxf(v1.y, 0.f);
            v1.z = fmaxf(v1.z, 0.f); v1.w = fmaxf(v1.w, 0.f);
        }
        *(float4*)(Cp + (size_t)m * ldc + n0 + tx * 8) = v0;
        *(float4*)(Cp + (size_t)m * ldc + n0 + tx * 8 + 4) = v1;
    }
}

template<int N, int SPLIT>
__global__ __launch_bounds__(256) void skinny_kernel(const float* __restrict__ A,
                                                     const float* __restrict__ B,
                                                     float* __restrict__ C, int K)
{
    int idx = blockIdx.x * 256 + threadIdx.x;
    int on = idx / SPLIT, ks = idx % SPLIT;
    int token = on / N, n = on % N;
    if (token >= NTOK) return;
    int kpp = K / SPLIT;
    const float* a = A + (size_t)token * K + ks * kpp;
    const float* b = B + (size_t)ks * kpp * N + n;
    float acc = 0.f;
    #pragma unroll 4
    for (int k = 0; k < kpp; k++) acc += a[k] * b[(size_t)k * N];
    if (SPLIT >= 2) acc += __shfl_xor_sync(~0u, acc, 1);
    if (SPLIT >= 4) acc += __shfl_xor_sync(~0u, acc, 2);
    if (ks == 0) C[on] = acc;
}

__global__ void init_hard_kernel()
{
    if (threadIdx.x < HH * EA) g_hard[threadIdx.x] = 0;
}

__global__ void argmax_kernel()
{
    int i = blockIdx.x * blockDim.x + threadIdx.x;
    if (i >= NTOK * HH) return;
    int n = i / HH, h = i % HH;
    const float* g = g_r + (size_t)n * (HH * EA) + h * EA;
    int best = 0; float bv = g[0];
    #pragma unroll
    for (int a = 1; a < EA; a++) if (g[a] > bv) { bv = g[a]; best = a; }
    g_idx[i] = best;
    atomicAdd(&g_hard[h * EA + best], 1);
}

__global__ void aux1_kernel()
{
    if (threadIdx.x != 0) return;
    float e[HH * EA];
    float tot = 0.f;
    for (int i = 0; i < HH * EA; i++) { e[i] = 0.01f * (float)g_hard[i] / (float)NTOK; tot += e[i]; }
    float a = 0.f;
    for (int i = 0; i < HH * EA; i++) { float pr = e[i] / (tot + 1e-9f); a += pr * pr; }
    g_aux[0] = a * (float)(EA * HH);
}

__global__ __launch_bounds__(64) void vproj_kernel(const float* __restrict__ Wv)
{
    int n = blockIdx.x, h = blockIdx.y, e = threadIdx.x;
    __shared__ float xs[DH];
    xs[e] = g_xln1[(size_t)n * DM + h * DH + e];
    __syncthreads();
    int a = g_idx[n * HH + h];
    const float* W = Wv + ((size_t)(h * EA + a)) * DH * DH;
    float acc = 0.f;
    #pragma unroll
    for (int d = 0; d < DH; d++) acc += xs[d] * W[d * DH + e];
    g_vproj[((size_t)h * NTOK + n) * DH + e] = acc;
}

__global__ __launch_bounds__(64) void oproj_kernel(const float* __restrict__ Wo,
                                                   const float* __restrict__ xres)
{
    int n = blockIdx.x, h = blockIdx.y, e = threadIdx.x;
    __shared__ float xs[DH];
    xs[e] = g_ao[((size_t)h * NTOK + n) * DH + e];
    __syncthreads();
    int a = g_idx[n * HH + h];
    const float* W = Wo + ((size_t)(h * EA + a)) * DH * DH;
    float acc = 0.f;
    #pragma unroll
    for (int d = 0; d < DH; d++) acc += xs[d] * W[d * DH + e];
    size_t off = (size_t)n * DM + h * DH + e;
    g_x1[off] = xres[off] + acc;
}

__global__ __launch_bounds__(256) void softmax_kernel(const float* __restrict__ mask)
{
    int row = blockIdx.x;
    int tid = threadIdx.x;
    int s = row & (SS - 1);
    float* p = g_p + (size_t)row * SS;
    const float* mr = mask + (size_t)s * SS;

    float m0v = mr[tid], m1v = mr[tid + 256];
    float v0 = p[tid] * 0.125f + m0v;
    float v1 = p[tid + 256] * 0.125f + m1v;

    __shared__ float red[8];
    int lane = tid & 31, w = tid >> 5;

    float mx = fmaxf(v0, v1);
    #pragma unroll
    for (int o = 16; o; o >>= 1) mx = fmaxf(mx, __shfl_xor_sync(~0u, mx, o));
    if (lane == 0) red[w] = mx;
    __syncthreads();
    if (w == 0) {
        float m = (lane < 8) ? red[lane] : -1e30f;
        #pragma unroll
        for (int o = 4; o; o >>= 1) m = fmaxf(m, __shfl_xor_sync(~0u, m, o));
        if (lane == 0) red[0] = m;
    }
    __syncthreads();
    mx = red[0];
    __syncthreads();

    float e0 = (m0v < -1e8f) ? 0.f : expf(v0 - mx);
    float e1 = (m1v < -1e8f) ? 0.f : expf(v1 - mx);
    float sm = e0 + e1;
    #pragma unroll
    for (int o = 16; o; o >>= 1) sm += __shfl_xor_sync(~0u, sm, o);
    if (lane == 0) red[w] = sm;
    __syncthreads();
    if (w == 0) {
        float m = (lane < 8) ? red[lane] : 0.f;
        #pragma unroll
        for (int o = 4; o; o >>= 1) m += __shfl_xor_sync(~0u, m, o);
        if (lane == 0) red[0] = m;
    }
    __syncthreads();
    float inv = 1.f / red[0];
    p[tid] = e0 * inv;
    p[tid + 256] = e1 * inv;
}

__global__ __launch_bounds__(256) void route_kernel()
{
    int tid = threadIdx.x;
    __shared__ int   s_e[NE];
    __shared__ float s_p[NE];
    __shared__ int   s_pos[NE];
    __shared__ int   s_keep[NE];
    __shared__ float s_imp[EF];
    __shared__ int   s_cnt[EF];

    for (int n = tid; n < NTOK; n += 256) {
        const float* g = g_gl + (size_t)n * EF;
        int i0 = 0; float v0 = g[0];
        #pragma unroll
        for (int j = 1; j < EF; j++) if (g[j] > v0) { v0 = g[j]; i0 = j; }
        int i1 = -1; float v1 = -1e30f;
        #pragma unroll
        for (int j = 0; j < EF; j++) { if (j == i0) continue; if (g[j] > v1) { v1 = g[j]; i1 = j; } }
        float e1 = expf(v1 - v0);
        float den = 1.f + e1;
        s_e[2 * n] = i0; s_e[2 * n + 1] = i1;
        s_p[2 * n] = 1.f / den; s_p[2 * n + 1] = e1 / den;
    }
    __syncthreads();
    if (tid == 0) {
        int cnt[EF] = {};
        for (int j = 0; j < NE; j++) {
            int e = s_e[j];
            int p = cnt[e]++;
            s_pos[j] = p;
            s_keep[j] = (p < CAP) ? 1 : 0;
        }
    }
    __syncthreads();
    if (tid < EF) { s_imp[tid] = 0.f; s_cnt[tid] = 0; }
    __syncthreads();
    for (int n = tid; n < NTOK; n += 256) {
        float p0 = s_p[2 * n]     * (float)s_keep[2 * n];
        float p1 = s_p[2 * n + 1] * (float)s_keep[2 * n + 1];
        float den = p0 + p1 + 1e-9f;
        float w0 = p0 / den, w1 = p1 / den;
        g_ew[2 * n] = w0;      g_ew[2 * n + 1] = w1;
        g_ee[2 * n] = s_e[2 * n];       g_ee[2 * n + 1] = s_e[2 * n + 1];
        g_epos[2 * n] = s_pos[2 * n];   g_epos[2 * n + 1] = s_pos[2 * n + 1];
        g_ekeep[2 * n] = s_keep[2 * n]; g_ekeep[2 * n + 1] = s_keep[2 * n + 1];
        if (s_keep[2 * n])     { atomicAdd(&s_cnt[s_e[2 * n]], 1);     atomicAdd(&s_imp[s_e[2 * n]], w0); }
        if (s_keep[2 * n + 1]) { atomicAdd(&s_cnt[s_e[2 * n + 1]], 1); atomicAdd(&s_imp[s_e[2 * n + 1]], w1); }
    }
    __syncthreads();
    if (tid == 0) {
        float ct = 0.f, it = 0.f;
        for (int e = 0; e < EF; e++) { ct += (float)s_cnt[e]; it += s_imp[e]; }
        float a = 0.f;
        for (int e = 0; e < EF; e++)
            a += ((float)s_cnt[e] / (ct + 1e-9f)) * (s_imp[e] / (it + 1e-9f));
        g_aux[1] = a * (float)EF;
    }
}

__global__ __launch_bounds__(192) void scatter_kernel()
{
    int j = blockIdx.x;
    if (!g_ekeep[j]) return;
    int tok = j >> 1;
    float4* dst = (float4*)(g_buf + ((size_t)g_ee[j] * CAP + g_epos[j]) * DM);
    const float4* src = (const float4*)(g_xln2 + (size_t)tok * DM);
    for (int d = threadIdx.x; d < DM / 4; d += 192) dst[d] = src[d];
}

__global__ __launch_bounds__(256) void output_kernel(float* __restrict__ out, int out_size)
{
    int n = blockIdx.x, tid = threadIdx.x;
    float w0 = g_ew[2 * n], w1 = g_ew[2 * n + 1];
    size_t o0 = ((size_t)g_ee[2 * n]     * CAP + g_epos[2 * n])     * DM;
    size_t o1 = ((size_t)g_ee[2 * n + 1] * CAP + g_epos[2 * n + 1]) * DM;
    bool k0 = g_ekeep[2 * n] != 0, k1 = g_ekeep[2 * n + 1] != 0;
    for (int d = tid; d < DM; d += 256) {
        float f = 0.f;
        if (k0) f += w0 * (g_ybuf[o0 + d] + g_ybuf[PSPLIT + o0 + d]
                         + g_ybuf[2 * PSPLIT + o0 + d] + g_ybuf[3 * PSPLIT + o0 + d]);
        if (k1) f += w1 * (g_ybuf[o1 + d] + g_ybuf[PSPLIT + o1 + d]
                         + g_ybuf[2 * PSPLIT + o1 + d] + g_ybuf[3 * PSPLIT + o1 + d]);
        out[(size_t)n * DM + d] = g_x1[(size_t)n * DM + d] + f;
    }
    if (n == 0 && tid == 0 && out_size > NTOK * DM)
        out[NTOK * DM] = g_aux[0] + g_aux[1];
}

extern "C" void kernel_launch(void* const* d_in, const int* in_sizes, int n_in,
                              void* d_out, int out_size)
{
    const float* x        = (const float*)d_in[0];
    const float* mask     = (const float*)d_in[1];
    const float* ln1_g    = (const float*)d_in[2];
    const float* ln1_b    = (const float*)d_in[3];
    const float* ln2_g    = (const float*)d_in[4];
    const float* ln2_b    = (const float*)d_in[5];
    const float* W_q      = (const float*)d_in[6];
    const float* W_k      = (const float*)d_in[7];
    const float* W_v      = (const float*)d_in[8];
    const float* W_o      = (const float*)d_in[9];
    const float* router_w = (const float*)d_in[10];
    const float* gate_w   = (const float*)d_in[11];
    const float* W1       = (const float*)d_in[12];
    const float* W2       = (const float*)d_in[13];
    float* out = (float*)d_out;

    float *p_xln1, *p_qk, *p_r, *p_p, *p_vproj, *p_ao, *p_x1, *p_xln2,
          *p_gl, *p_buf, *p_hmid, *p_ybuf;
    cudaGetSymbolAddress((void**)&p_xln1,  g_xln1);
    cudaGetSymbolAddress((void**)&p_qk,    g_qk);
    cudaGetSymbolAddress((void**)&p_r,     g_r);
    cudaGetSymbolAddress((void**)&p_p,     g_p);
    cudaGetSymbolAddress((void**)&p_vproj, g_vproj);
    cudaGetSymbolAddress((void**)&p_ao,    g_ao);
    cudaGetSymbolAddress((void**)&p_x1,    g_x1);
    cudaGetSymbolAddress((void**)&p_xln2,  g_xln2);
    cudaGetSymbolAddress((void**)&p_gl,    g_gl);
    cudaGetSymbolAddress((void**)&p_buf,   g_buf);
    cudaGetSymbolAddress((void**)&p_hmid,  g_hmid);
    cudaGetSymbolAddress((void**)&p_ybuf,  g_ybuf);
    float* p_q = p_qk;
    float* p_k = p_qk + (size_t)NTOK * DM;

    init_hard_kernel<<<1, 64>>>();
    ln_kernel<<<NTOK, 256>>>(x, ln1_g, ln1_b, p_xln1);

    gemm_t<64,64,0,0,0,1,0><<<dim3(12, 16, 2), 64>>>(p_xln1, W_q, W_k, p_qk,
        NTOK, DM, DM, DM, DM, DM, 0, 0, (size_t)NTOK*DM);

    skinny_kernel<HH*EA,1><<<NTOK*HH*EA/256, 256>>>(p_xln1, router_w, p_r, DM);

    argmax_kernel<<<(NTOK*HH + 255)/256, 256>>>();
    aux1_kernel<<<1, 32>>>();

    vproj_kernel<<<dim3(NTOK, HH), 64>>>(W_v);

    gemm_t<64,64,0,1,0,2,1><<<dim3(8, 8, HH*BB), 64>>>(p_q, p_k, nullptr, p_p,
        SS, SS, DH, DM, DM, SS, 0, 0, 0);
    softmax_kernel<<<HH*BB*SS, 256>>>(mask);

    gemm_t<64,64,1,0,0,0,2><<<dim3(1, 8, HH*BB), 64>>>(p_p, p_vproj, nullptr, p_ao,
        SS, DH, SS, SS, DH, DH, (size_t)SS*SS, (size_t)SS*DH, (size_t)SS*DH);

    oproj_kernel<<<dim3(NTOK, HH), 64>>>(W_o, x);

    ln_kernel<<<NTOK, 256>>>(p_x1, ln2_g, ln2_b, p_xln2);
    skinny_kernel<EF,4><<<NTOK*EF*4/256, 256>>>(p_xln2, gate_w, p_gl, DM);

    route_kernel<<<1, 256>>>();
    scatter_kernel<<<NE, 192>>>();

    gemm_t<32,128,0,0,1,0,0><<<dim3(24, 5, EF), 64>>>(p_buf, W1, nullptr, p_hmid,
        CAP, DFF, DM, DM, DFF, DFF, (size_t)CAP*DM, (size_t)DM*DFF, (size_t)CAP*DFF);

    gemm_t<32,128,0,0,0,3,0><<<dim3(6, 5, EF*4), 64>>>(p_hmid, W2, nullptr, p_ybuf,
        CAP, DM, DFF/4, DFF, DM, DM, (size_t)CAP*DFF, (size_t)DFF*DM, (size_t)CAP*DM);

    output_kernel<<<NTOK, 256>>>(out, out_size);
}

// round 4
// speedup vs baseline: 1.6495x; 1.0297x over previous
#include <cuda_runtime.h>
#include <math.h>

#define BB   2
#define SS   512
#define DM   768
#define HH   12
#define DH   64
#define EA   4
#define EF   8
#define DFF  3072
#define NTOK (BB*SS)
#define CAP  160
#define NE   (NTOK*2)
#define PSPLIT ((size_t)EF*CAP*DM)

__device__ float g_xln1[NTOK*DM];
__device__ float g_qk[2*NTOK*DM];
__device__ float g_r[NTOK*HH*EA];
__device__ int   g_idx[NTOK*HH];
__device__ int   g_hard[HH*EA];
__device__ float g_vproj[HH*NTOK*DH];
__device__ float g_p[HH*BB*SS*SS];
__device__ float g_ao[HH*NTOK*DH];
__device__ float g_x1[NTOK*DM];
__device__ float g_xln2[NTOK*DM];
__device__ float g_gl[NTOK*EF];
__device__ int   g_ee[NE];
__device__ int   g_epos[NE];
__device__ float g_ew[NE];
__device__ int   g_ekeep[NE];
__device__ float g_buf[EF*CAP*DM];
__device__ float g_hmid[EF*CAP*DFF];
__device__ float g_ybuf[4*EF*CAP*DM];
__device__ float g_aux[2];

__device__ __forceinline__ unsigned long long pk2(float lo, float hi) {
    unsigned long long r;
    asm("mov.b64 %0, {%1,%2};" : "=l"(r) : "f"(lo), "f"(hi));
    return r;
}
__device__ __forceinline__ void upk2(unsigned long long v, float& lo, float& hi) {
    asm("mov.b64 {%0,%1}, %2;" : "=f"(lo), "=f"(hi) : "l"(v));
}
__device__ __forceinline__ void fma2(unsigned long long& d, unsigned long long a,
                                     unsigned long long b) {
    asm("fma.rn.f32x2 %0, %1, %2, %0;" : "+l"(d) : "l"(a), "l"(b));
}

// ---------------- LayerNorm ----------------
__global__ __launch_bounds__(256) void ln_kernel(const float* __restrict__ x,
                                                 const float* __restrict__ g,
                                                 const float* __restrict__ b,
                                                 float* __restrict__ out)
{
    int n = blockIdx.x;
    const float* row = x + (size_t)n * DM;
    float s = 0.f, ss = 0.f;
    for (int d = threadIdx.x; d < DM; d += 256) {
        float v = row[d];
        s += v; ss += v * v;
    }
    __shared__ float shs[8], shq[8];
    int lane = threadIdx.x & 31, wid = threadIdx.x >> 5;
    #pragma unroll
    for (int o = 16; o; o >>= 1) { s += __shfl_xor_sync(~0u, s, o); ss += __shfl_xor_sync(~0u, ss, o); }
    if (lane == 0) { shs[wid] = s; shq[wid] = ss; }
    __syncthreads();
    if (threadIdx.x == 0) {
        float ts = 0, tq = 0;
        for (int i = 0; i < 8; i++) { ts += shs[i]; tq += shq[i]; }
        shs[0] = ts; shq[0] = tq;
    }
    __syncthreads();
    float mu = shs[0] / DM;
    float var = shq[0] / DM - mu * mu;
    float inv = rsqrtf(var + 1e-5f);
    for (int d = threadIdx.x; d < DM; d += 256)
        out[(size_t)n * DM + d] = (row[d] - mu) * inv * g[d] + b[d];
}

// ---------------- big tiled GEMM (unchanged from R3) ----------------
template<int TM, int TN, int TA, int TB, int RELU, int LAYOUT, int TRI>
__global__ __launch_bounds__(64) void gemm_t(
    const float* __restrict__ A, const float* __restrict__ B0,
    const float* __restrict__ B1, float* __restrict__ C,
    int M, int N, int K, int lda, int ldb, int ldc,
    size_t sA, size_t sB, size_t sC)
{
    const float* Ap = A;
    const float* Bp = B0;
    float* Cp = C;
    int z = blockIdx.z;
    if (LAYOUT == 0) {
        Ap += (size_t)z * sA; Bp += (size_t)z * sB; Cp += (size_t)z * sC;
    } else if (LAYOUT == 1) {
        Bp = z ? B1 : B0; Cp += (size_t)z * sC;
    } else if (LAYOUT == 2) {
        int b = z & 1, h = z >> 1;
        Ap += (size_t)(b * SS) * lda + (size_t)h * DH;
        Bp += (size_t)(b * SS) * ldb + (size_t)h * DH;
        Cp += (size_t)z * SS * SS;
    } else {
        int e = z >> 2, part = z & 3;
        Ap += (size_t)e * sA + (size_t)part * K;
        Bp += (size_t)e * sB + (size_t)part * K * ldb;
        Cp += (size_t)part * PSPLIT + (size_t)e * sC;
    }

    int m0 = blockIdx.y * TM, n0 = blockIdx.x * TN;
    if (TRI == 1 && n0 >= m0 + TM) return;

    int tid = threadIdx.x;
    constexpr int TX = TN / 8;
    int ty = tid / TX, tx = tid % TX;

    __shared__ float As[2][8][TM + 4];
    __shared__ float Bs[2][8][TN + 4];

    constexpr int AIT = (2 * TM) / 64;
    constexpr int BIT = (2 * TN) / 64;

    float4 pa[AIT], pb[BIT];

    auto loadA = [&](int k0) {
        #pragma unroll
        for (int r = 0; r < AIT; r++) {
            int idx = tid + r * 64;
            if (TA == 0) {
                int row = idx >> 1, kh = (idx & 1) * 4;
                pa[r] = *(const float4*)(Ap + (size_t)(m0 + row) * lda + k0 + kh);
            } else {
                int k = idx / (TM / 4), m4 = (idx % (TM / 4)) * 4;
                pa[r] = *(const float4*)(Ap + (size_t)(k0 + k) * lda + m0 + m4);
            }
        }
    };
    auto storeA = [&](int buf) {
        #pragma unroll
        for (int r = 0; r < AIT; r++) {
            int idx = tid + r * 64;
            if (TA == 0) {
                int row = idx >> 1, kh = (idx & 1) * 4;
                As[buf][kh + 0][row] = pa[r].x; As[buf][kh + 1][row] = pa[r].y;
                As[buf][kh + 2][row] = pa[r].z; As[buf][kh + 3][row] = pa[r].w;
            } else {
                int k = idx / (TM / 4), m4 = (idx % (TM / 4)) * 4;
                *(float4*)&As[buf][k][m4] = pa[r];
            }
        }
    };
    auto loadB = [&](int k0) {
        #pragma unroll
        for (int r = 0; r < BIT; r++) {
            int idx = tid + r * 64;
            if (TB == 0) {
                int k = idx / (TN / 4), n4 = (idx % (TN / 4)) * 4;
                pb[r] = *(const float4*)(Bp + (size_t)(k0 + k) * ldb + n0 + n4);
            } else {
                int n = idx >> 1, kh = (idx & 1) * 4;
                pb[r] = *(const float4*)(Bp + (size_t)(n0 + n) * ldb + k0 + kh);
            }
        }
    };
    auto storeB = [&](int buf) {
        #pragma unroll
        for (int r = 0; r < BIT; r++) {
            int idx = tid + r * 64;
            if (TB == 0) {
                int k = idx / (TN / 4), n4 = (idx % (TN / 4)) * 4;
                *(float4*)&Bs[buf][k][n4] = pb[r];
            } else {
                int n = idx >> 1, kh = (idx & 1) * 4;
                Bs[buf][kh + 0][n] = pb[r].x; Bs[buf][kh + 1][n] = pb[r].y;
                Bs[buf][kh + 2][n] = pb[r].z; Bs[buf][kh + 3][n] = pb[r].w;
            }
        }
    };

    unsigned long long acc[8][4];
    #pragma unroll
    for (int i = 0; i < 8; i++)
        #pragma unroll
        for (int j = 0; j < 4; j++) acc[i][j] = 0ull;

    int kbeg = (TRI == 2) ? m0 : 0;
    int nk = (K - kbeg) >> 3;

    loadA(kbeg); storeA(0);
    loadB(kbeg); storeB(0);
    __syncthreads();

    for (int t = 0; t < nk; t++) {
        int cur = t & 1;
        bool has = (t + 1 < nk);
        if (has) { loadA(kbeg + (t + 1) * 8); loadB(kbeg + (t + 1) * 8); }
        #pragma unroll
        for (int k = 0; k < 8; k++) {
            float4 a0 = *(const float4*)&As[cur][k][ty * 8];
            float4 a1 = *(const float4*)&As[cur][k][ty * 8 + 4];
            float4 b0 = *(const float4*)&Bs[cur][k][tx * 8];
            float4 b1 = *(const float4*)&Bs[cur][k][tx * 8 + 4];
            unsigned long long bp[4] = {pk2(b0.x, b0.y), pk2(b0.z, b0.w),
                                        pk2(b1.x, b1.y), pk2(b1.z, b1.w)};
            float av[8] = {a0.x, a0.y, a0.z, a0.w, a1.x, a1.y, a1.z, a1.w};
            #pragma unroll
            for (int i = 0; i < 8; i++) {
                unsigned long long ap = pk2(av[i], av[i]);
                #pragma unroll
                for (int j = 0; j < 4; j++) fma2(acc[i][j], ap, bp[j]);
            }
        }
        if (has) { storeA(cur ^ 1); storeB(cur ^ 1); }
        __syncthreads();
    }

    #pragma unroll
    for (int i = 0; i < 8; i++) {
        int m = m0 + ty * 8 + i;
        float4 v0, v1;
        upk2(acc[i][0], v0.x, v0.y); upk2(acc[i][1], v0.z, v0.w);
        upk2(acc[i][2], v1.x, v1.y); upk2(acc[i][3], v1.z, v1.w);
        if (RELU) {
            v0.x = fmaxf(v0.x, 0.f); v0.y = fmaxf(v0.y, 0.f);
            v0.z = fmaxf(v0.z, 0.f); v0.w = fmaxf(v0.w, 0.f);
            v1.x = fmaxf(v1.x, 0.f); v1.y = fmaxf(v1.y, 0.f);
            v1.z = fmaxf(v1.z, 0.f); v1.w = fmaxf(v1.w, 0.f);
        }
        *(float4*)(Cp + (size_t)m * ldc + n0 + tx * 8) = v0;
        *(float4*)(Cp + (size_t)m * ldc + n0 + tx * 8 + 4) = v1;
    }
}

// ---------------- smem-tiled small-N GEMM (router N=48, gate N=8) ----------------
template<int N>
__global__ __launch_bounds__(256) void smallgemm_kernel(const float* __restrict__ A,
                                                        const float* __restrict__ B,
                                                        float* __restrict__ C)
{
    __shared__ float As[32][68];
    __shared__ float Bs[64 * N];
    int tid = threadIdx.x;
    int n0 = blockIdx.x * 32;
    constexpr int OPT = N / 8;               // outputs per thread (6 or 1)
    int t = tid >> 3, j0 = (tid & 7) * OPT;
    float acc[OPT] = {};

    for (int kc = 0; kc < DM; kc += 64) {
        __syncthreads();
        for (int i = tid; i < 32 * 16; i += 256) {
            int tok = i >> 4, q = (i & 15) * 4;
            *(float4*)&As[tok][q] = *(const float4*)(A + (size_t)(n0 + tok) * DM + kc + q);
        }
        const float4* Bg = (const float4*)(B + (size_t)kc * N);
        float4* Bs4 = (float4*)Bs;
        for (int i = tid; i < 16 * N; i += 256) Bs4[i] = Bg[i];
        __syncthreads();
        #pragma unroll 8
        for (int k = 0; k < 64; k++) {
            float a = As[t][k];
            #pragma unroll
            for (int j = 0; j < OPT; j++) acc[j] += a * Bs[k * N + j0 + j];
        }
    }
    #pragma unroll
    for (int j = 0; j < OPT; j++)
        C[(size_t)(n0 + t) * N + j0 + j] = acc[j];
}

// ---------------- expert V/O projections: all-expert W cached in smem ----------------
// grid (NTOK/32, HH), 256 threads, dynamic smem = 4*64*64 + 32*68 floats
#define PROJ_SMEM ((4*DH*DH + 32*68) * 4)
template<int OPROJ>
__global__ __launch_bounds__(256) void proj_kernel(const float* __restrict__ W,
                                                   const float* __restrict__ xres)
{
    extern __shared__ float sm[];
    float* sW = sm;                 // 4 experts x 64 x 64
    float* sx = sm + 4 * DH * DH;   // 32 tokens x 68 (padded)
    int h = blockIdx.y, n0 = blockIdx.x * 32;
    int tid = threadIdx.x;

    const float4* Wg = (const float4*)(W + (size_t)h * EA * DH * DH);
    float4* sW4 = (float4*)sW;
    #pragma unroll
    for (int i = 0; i < 16; i++) sW4[tid + i * 256] = Wg[tid + i * 256];

    for (int i = tid; i < 32 * DH; i += 256) {
        int tok = i >> 6, d = i & 63;
        float v;
        if (OPROJ) v = g_ao[((size_t)h * NTOK + n0 + tok) * DH + d];
        else       v = g_xln1[(size_t)(n0 + tok) * DM + h * DH + d];
        sx[tok * 68 + d] = v;
    }
    __syncthreads();

    int t = tid >> 3;
    int e0 = (tid & 7) * 8;
    int n = n0 + t;
    int a = g_idx[n * HH + h];
    const float* Wt = sW + a * DH * DH;
    float acc[8] = {};
    #pragma unroll 8
    for (int d = 0; d < DH; d++) {
        float xv = sx[t * 68 + d];
        float4 w0 = *(const float4*)&Wt[d * DH + e0];
        float4 w1 = *(const float4*)&Wt[d * DH + e0 + 4];
        acc[0] += xv * w0.x; acc[1] += xv * w0.y;
        acc[2] += xv * w0.z; acc[3] += xv * w0.w;
        acc[4] += xv * w1.x; acc[5] += xv * w1.y;
        acc[6] += xv * w1.z; acc[7] += xv * w1.w;
    }
    if (OPROJ) {
        size_t off = (size_t)n * DM + h * DH + e0;
        float4 r0 = *(const float4*)(xres + off);
        float4 r1 = *(const float4*)(xres + off + 4);
        float4 v0 = make_float4(r0.x + acc[0], r0.y + acc[1], r0.z + acc[2], r0.w + acc[3]);
        float4 v1 = make_float4(r1.x + acc[4], r1.y + acc[5], r1.z + acc[6], r1.w + acc[7]);
        *(float4*)(g_x1 + off) = v0;
        *(float4*)(g_x1 + off + 4) = v1;
    } else {
        size_t off = ((size_t)h * NTOK + n) * DH + e0;
        *(float4*)(g_vproj + off) = make_float4(acc[0], acc[1], acc[2], acc[3]);
        *(float4*)(g_vproj + off + 4) = make_float4(acc[4], acc[5], acc[6], acc[7]);
    }
}

// ---------------- routing / small kernels ----------------
__global__ void init_hard_kernel()
{
    if (threadIdx.x < HH * EA) g_hard[threadIdx.x] = 0;
}

__global__ void argmax_kernel()
{
    int i = blockIdx.x * blockDim.x + threadIdx.x;
    if (i >= NTOK * HH) return;
    int n = i / HH, h = i % HH;
    const float* g = g_r + (size_t)n * (HH * EA) + h * EA;
    int best = 0; float bv = g[0];
    #pragma unroll
    for (int a = 1; a < EA; a++) if (g[a] > bv) { bv = g[a]; best = a; }
    g_idx[i] = best;
    atomicAdd(&g_hard[h * EA + best], 1);
}

__global__ void aux1_kernel()
{
    if (threadIdx.x != 0) return;
    float e[HH * EA];
    float tot = 0.f;
    for (int i = 0; i < HH * EA; i++) { e[i] = 0.01f * (float)g_hard[i] / (float)NTOK; tot += e[i]; }
    float a = 0.f;
    for (int i = 0; i < HH * EA; i++) { float pr = e[i] / (tot + 1e-9f); a += pr * pr; }
    g_aux[0] = a * (float)(EA * HH);
}

__global__ __launch_bounds__(256) void softmax_kernel(const float* __restrict__ mask)
{
    int row = blockIdx.x;
    int tid = threadIdx.x;
    int s = row & (SS - 1);
    float* p = g_p + (size_t)row * SS;
    const float* mr = mask + (size_t)s * SS;

    float m0v = mr[tid], m1v = mr[tid + 256];
    float v0 = p[tid] * 0.125f + m0v;
    float v1 = p[tid + 256] * 0.125f + m1v;

    __shared__ float red[8];
    int lane = tid & 31, w = tid >> 5;

    float mx = fmaxf(v0, v1);
    #pragma unroll
    for (int o = 16; o; o >>= 1) mx = fmaxf(mx, __shfl_xor_sync(~0u, mx, o));
    if (lane == 0) red[w] = mx;
    __syncthreads();
    if (w == 0) {
        float m = (lane < 8) ? red[lane] : -1e30f;
        #pragma unroll
        for (int o = 4; o; o >>= 1) m = fmaxf(m, __shfl_xor_sync(~0u, m, o));
        if (lane == 0) red[0] = m;
    }
    __syncthreads();
    mx = red[0];
    __syncthreads();

    float e0 = (m0v < -1e8f) ? 0.f : expf(v0 - mx);
    float e1 = (m1v < -1e8f) ? 0.f : expf(v1 - mx);
    float sm = e0 + e1;
    #pragma unroll
    for (int o = 16; o; o >>= 1) sm += __shfl_xor_sync(~0u, sm, o);
    if (lane == 0) red[w] = sm;
    __syncthreads();
    if (w == 0) {
        float m = (lane < 8) ? red[lane] : 0.f;
        #pragma unroll
        for (int o = 4; o; o >>= 1) m += __shfl_xor_sync(~0u, m, o);
        if (lane == 0) red[0] = m;
    }
    __syncthreads();
    float inv = 1.f / red[0];
    p[tid] = e0 * inv;
    p[tid + 256] = e1 * inv;
}

__global__ __launch_bounds__(256) void route_kernel()
{
    int tid = threadIdx.x;
    __shared__ int   s_e[NE];
    __shared__ float s_p[NE];
    __shared__ int   s_pos[NE];
    __shared__ int   s_keep[NE];
    __shared__ float s_imp[EF];
    __shared__ int   s_cnt[EF];

    for (int n = tid; n < NTOK; n += 256) {
        const float* g = g_gl + (size_t)n * EF;
        int i0 = 0; float v0 = g[0];
        #pragma unroll
        for (int j = 1; j < EF; j++) if (g[j] > v0) { v0 = g[j]; i0 = j; }
        int i1 = -1; float v1 = -1e30f;
        #pragma unroll
        for (int j = 0; j < EF; j++) { if (j == i0) continue; if (g[j] > v1) { v1 = g[j]; i1 = j; } }
        float e1 = expf(v1 - v0);
        float den = 1.f + e1;
        s_e[2 * n] = i0; s_e[2 * n + 1] = i1;
        s_p[2 * n] = 1.f / den; s_p[2 * n + 1] = e1 / den;
    }
    __syncthreads();
    if (tid == 0) {
        int cnt[EF] = {};
        for (int j = 0; j < NE; j++) {
            int e = s_e[j];
            int p = cnt[e]++;
            s_pos[j] = p;
            s_keep[j] = (p < CAP) ? 1 : 0;
        }
    }
    __syncthreads();
    if (tid < EF) { s_imp[tid] = 0.f; s_cnt[tid] = 0; }
    __syncthreads();
    for (int n = tid; n < NTOK; n += 256) {
        float p0 = s_p[2 * n]     * (float)s_keep[2 * n];
        float p1 = s_p[2 * n + 1] * (float)s_keep[2 * n + 1];
        float den = p0 + p1 + 1e-9f;
        float w0 = p0 / den, w1 = p1 / den;
        g_ew[2 * n] = w0;      g_ew[2 * n + 1] = w1;
        g_ee[2 * n] = s_e[2 * n];       g_ee[2 * n + 1] = s_e[2 * n + 1];
        g_epos[2 * n] = s_pos[2 * n];   g_epos[2 * n + 1] = s_pos[2 * n + 1];
        g_ekeep[2 * n] = s_keep[2 * n]; g_ekeep[2 * n + 1] = s_keep[2 * n + 1];
        if (s_keep[2 * n])     { atomicAdd(&s_cnt[s_e[2 * n]], 1);     atomicAdd(&s_imp[s_e[2 * n]], w0); }
        if (s_keep[2 * n + 1]) { atomicAdd(&s_cnt[s_e[2 * n + 1]], 1); atomicAdd(&s_imp[s_e[2 * n + 1]], w1); }
    }
    __syncthreads();
    if (tid == 0) {
        float ct = 0.f, it = 0.f;
        for (int e = 0; e < EF; e++) { ct += (float)s_cnt[e]; it += s_imp[e]; }
        float a = 0.f;
        for (int e = 0; e < EF; e++)
            a += ((float)s_cnt[e] / (ct + 1e-9f)) * (s_imp[e] / (it + 1e-9f));
        g_aux[1] = a * (float)EF;
    }
}

__global__ __launch_bounds__(192) void scatter_kernel()
{
    int j = blockIdx.x;
    if (!g_ekeep[j]) return;
    int tok = j >> 1;
    float4* dst = (float4*)(g_buf + ((size_t)g_ee[j] * CAP + g_epos[j]) * DM);
    const float4* src = (const float4*)(g_xln2 + (size_t)tok * DM);
    for (int d = threadIdx.x; d < DM / 4; d += 192) dst[d] = src[d];
}

__global__ __launch_bounds__(256) void output_kernel(float* __restrict__ out, int out_size)
{
    int n = blockIdx.x, tid = threadIdx.x;
    float w0 = g_ew[2 * n], w1 = g_ew[2 * n + 1];
    size_t o0 = ((size_t)g_ee[2 * n]     * CAP + g_epos[2 * n])     * DM;
    size_t o1 = ((size_t)g_ee[2 * n + 1] * CAP + g_epos[2 * n + 1]) * DM;
    bool k0 = g_ekeep[2 * n] != 0, k1 = g_ekeep[2 * n + 1] != 0;
    for (int d = tid; d < DM; d += 256) {
        float f = 0.f;
        if (k0) f += w0 * (g_ybuf[o0 + d] + g_ybuf[PSPLIT + o0 + d]
                         + g_ybuf[2 * PSPLIT + o0 + d] + g_ybuf[3 * PSPLIT + o0 + d]);
        if (k1) f += w1 * (g_ybuf[o1 + d] + g_ybuf[PSPLIT + o1 + d]
                         + g_ybuf[2 * PSPLIT + o1 + d] + g_ybuf[3 * PSPLIT + o1 + d]);
        out[(size_t)n * DM + d] = g_x1[(size_t)n * DM + d] + f;
    }
    if (n == 0 && tid == 0 && out_size > NTOK * DM)
        out[NTOK * DM] = g_aux[0] + g_aux[1];
}

// ---------------- host launcher ----------------
extern "C" void kernel_launch(void* const* d_in, const int* in_sizes, int n_in,
                              void* d_out, int out_size)
{
    const float* x        = (const float*)d_in[0];
    const float* mask     = (const float*)d_in[1];
    const float* ln1_g    = (const float*)d_in[2];
    const float* ln1_b    = (const float*)d_in[3];
    const float* ln2_g    = (const float*)d_in[4];
    const float* ln2_b    = (const float*)d_in[5];
    const float* W_q      = (const float*)d_in[6];
    const float* W_k      = (const float*)d_in[7];
    const float* W_v      = (const float*)d_in[8];
    const float* W_o      = (const float*)d_in[9];
    const float* router_w = (const float*)d_in[10];
    const float* gate_w   = (const float*)d_in[11];
    const float* W1       = (const float*)d_in[12];
    const float* W2       = (const float*)d_in[13];
    float* out = (float*)d_out;

    float *p_xln1, *p_qk, *p_r, *p_p, *p_vproj, *p_ao, *p_x1, *p_xln2,
          *p_gl, *p_buf, *p_hmid, *p_ybuf;
    cudaGetSymbolAddress((void**)&p_xln1,  g_xln1);
    cudaGetSymbolAddress((void**)&p_qk,    g_qk);
    cudaGetSymbolAddress((void**)&p_r,     g_r);
    cudaGetSymbolAddress((void**)&p_p,     g_p);
    cudaGetSymbolAddress((void**)&p_vproj, g_vproj);
    cudaGetSymbolAddress((void**)&p_ao,    g_ao);
    cudaGetSymbolAddress((void**)&p_x1,    g_x1);
    cudaGetSymbolAddress((void**)&p_xln2,  g_xln2);
    cudaGetSymbolAddress((void**)&p_gl,    g_gl);
    cudaGetSymbolAddress((void**)&p_buf,   g_buf);
    cudaGetSymbolAddress((void**)&p_hmid,  g_hmid);
    cudaGetSymbolAddress((void**)&p_ybuf,  g_ybuf);
    float* p_q = p_qk;
    float* p_k = p_qk + (size_t)NTOK * DM;

    static int smem_set = 0;
    if (!smem_set) {
        cudaFuncSetAttribute(proj_kernel<0>, cudaFuncAttributeMaxDynamicSharedMemorySize, PROJ_SMEM);
        cudaFuncSetAttribute(proj_kernel<1>, cudaFuncAttributeMaxDynamicSharedMemorySize, PROJ_SMEM);
        smem_set = 1;
    }

    init_hard_kernel<<<1, 64>>>();
    ln_kernel<<<NTOK, 256>>>(x, ln1_g, ln1_b, p_xln1);

    gemm_t<64,64,0,0,0,1,0><<<dim3(12, 16, 2), 64>>>(p_xln1, W_q, W_k, p_qk,
        NTOK, DM, DM, DM, DM, DM, 0, 0, (size_t)NTOK*DM);

    smallgemm_kernel<HH*EA><<<NTOK/32, 256>>>(p_xln1, router_w, p_r);

    argmax_kernel<<<(NTOK*HH + 255)/256, 256>>>();
    aux1_kernel<<<1, 32>>>();

    proj_kernel<0><<<dim3(NTOK/32, HH), 256, PROJ_SMEM>>>(W_v, nullptr);

    gemm_t<64,64,0,1,0,2,1><<<dim3(8, 8, HH*BB), 64>>>(p_q, p_k, nullptr, p_p,
        SS, SS, DH, DM, DM, SS, 0, 0, 0);
    softmax_kernel<<<HH*BB*SS, 256>>>(mask);

    gemm_t<64,64,1,0,0,0,2><<<dim3(1, 8, HH*BB), 64>>>(p_p, p_vproj, nullptr, p_ao,
        SS, DH, SS, SS, DH, DH, (size_t)SS*SS, (size_t)SS*DH, (size_t)SS*DH);

    proj_kernel<1><<<dim3(NTOK/32, HH), 256, PROJ_SMEM>>>(W_o, x);

    ln_kernel<<<NTOK, 256>>>(p_x1, ln2_g, ln2_b, p_xln2);
    smallgemm_kernel<EF><<<NTOK/32, 256>>>(p_xln2, gate_w, p_gl);

    route_kernel<<<1, 256>>>();
    scatter_kernel<<<NE, 192>>>();

    gemm_t<32,128,0,0,1,0,0><<<dim3(24, 5, EF), 64>>>(p_buf, W1, nullptr, p_hmid,
        CAP, DFF, DM, DM, DFF, DFF, (size_t)CAP*DM, (size_t)DM*DFF, (size_t)CAP*DFF);

    gemm_t<32,128,0,0,0,3,0><<<dim3(6, 5, EF*4), 64>>>(p_hmid, W2, nullptr, p_ybuf,
        CAP, DM, DFF/4, DFF, DM, DM, (size_t)CAP*DFF, (size_t)DFF*DM, (size_t)CAP*DM);

    output_kernel<<<NTOK, 256>>>(out, out_size);
}

// round 5
// speedup vs baseline: 2.1923x; 1.3291x over previous
#include <cuda_runtime.h>
#include <math.h>

#define BB   2
#define SS   512
#define DM   768
#define HH   12
#define DH   64
#define EA   4
#define EF   8
#define DFF  3072
#define NTOK (BB*SS)
#define CAP  160
#define NE   (NTOK*2)
#define KSP  6                      // smallgemm K-split
#define PSPLIT ((size_t)EF*CAP*DM)

__device__ float g_xln1[NTOK*DM];
__device__ float g_qk[2*NTOK*DM];
__device__ float g_rp[KSP*NTOK*HH*EA];
__device__ float g_glp[KSP*NTOK*EF];
__device__ int   g_idx[NTOK*HH];
__device__ int   g_hard[HH*EA];
__device__ float g_vproj[HH*NTOK*DH];
__device__ float g_p[HH*BB*SS*SS];
__device__ float g_ao[HH*NTOK*DH];
__device__ float g_x1[NTOK*DM];
__device__ float g_xln2[NTOK*DM];
__device__ int   g_tei[NE];
__device__ float g_tpw[NE];
__device__ int   g_ee[NE];
__device__ int   g_epos[NE];
__device__ float g_ew[NE];
__device__ int   g_ekeep[NE];
__device__ float g_buf[EF*CAP*DM];
__device__ float g_hmid[EF*CAP*DFF];
__device__ float g_ybuf[4*EF*CAP*DM];
__device__ float g_aux[2];

__device__ __forceinline__ unsigned long long pk2(float lo, float hi) {
    unsigned long long r;
    asm("mov.b64 %0, {%1,%2};" : "=l"(r) : "f"(lo), "f"(hi));
    return r;
}
__device__ __forceinline__ void upk2(unsigned long long v, float& lo, float& hi) {
    asm("mov.b64 {%0,%1}, %2;" : "=f"(lo), "=f"(hi) : "l"(v));
}
__device__ __forceinline__ void fma2(unsigned long long& d, unsigned long long a,
                                     unsigned long long b) {
    asm("fma.rn.f32x2 %0, %1, %2, %0;" : "+l"(d) : "l"(a), "l"(b));
}
__device__ __forceinline__ void cp16(void* smem, const void* g) {
    unsigned s = (unsigned)__cvta_generic_to_shared(smem);
    asm volatile("cp.async.cg.shared.global [%0], [%1], 16;" :: "r"(s), "l"(g));
}
__device__ __forceinline__ void cp_commit() {
    asm volatile("cp.async.commit_group;");
}
__device__ __forceinline__ void cp_wait0() {
    asm volatile("cp.async.wait_group 0;");
}

// ---------------- LayerNorm ----------------
__global__ __launch_bounds__(256) void ln_kernel(const float* __restrict__ x,
                                                 const float* __restrict__ g,
                                                 const float* __restrict__ b,
                                                 float* __restrict__ out)
{
    int n = blockIdx.x;
    const float* row = x + (size_t)n * DM;
    float s = 0.f, ss = 0.f;
    for (int d = threadIdx.x; d < DM; d += 256) {
        float v = row[d];
        s += v; ss += v * v;
    }
    __shared__ float shs[8], shq[8];
    int lane = threadIdx.x & 31, wid = threadIdx.x >> 5;
    #pragma unroll
    for (int o = 16; o; o >>= 1) { s += __shfl_xor_sync(~0u, s, o); ss += __shfl_xor_sync(~0u, ss, o); }
    if (lane == 0) { shs[wid] = s; shq[wid] = ss; }
    __syncthreads();
    if (threadIdx.x == 0) {
        float ts = 0, tq = 0;
        for (int i = 0; i < 8; i++) { ts += shs[i]; tq += shq[i]; }
        shs[0] = ts; shq[0] = tq;
    }
    __syncthreads();
    float mu = shs[0] / DM;
    float var = shq[0] / DM - mu * mu;
    float inv = rsqrtf(var + 1e-5f);
    for (int d = threadIdx.x; d < DM; d += 256)
        out[(size_t)n * DM + d] = (row[d] - mu) * inv * g[d] + b[d];
}

// ---------------------------------------------------------------------------
// 64-thread SGEMM, K-stage 16, cp.async for non-transposed operands.
// TA: 0 = A row-major (reg transpose), 1 = A K-major (cp.async)
// TB: 0 = B row-major (cp.async),      1 = B N-major (reg transpose)
// LAYOUT: 0 z-batch, 1 dual(B0/B1), 2 scores slices, 3 split-K4 experts
// TRI: 0 none, 1 skip upper tiles, 2 k-loop from m0
// ---------------------------------------------------------------------------
template<int TM, int TN, int TA, int TB, int RELU, int LAYOUT, int TRI>
__global__ __launch_bounds__(64) void gemm_t(
    const float* __restrict__ A, const float* __restrict__ B0,
    const float* __restrict__ B1, float* __restrict__ C,
    int M, int N, int K, int lda, int ldb, int ldc,
    size_t sA, size_t sB, size_t sC)
{
    const float* Ap = A;
    const float* Bp = B0;
    float* Cp = C;
    int z = blockIdx.z;
    if (LAYOUT == 0) {
        Ap += (size_t)z * sA; Bp += (size_t)z * sB; Cp += (size_t)z * sC;
    } else if (LAYOUT == 1) {
        Bp = z ? B1 : B0; Cp += (size_t)z * sC;
    } else if (LAYOUT == 2) {
        int b = z & 1, h = z >> 1;
        Ap += (size_t)(b * SS) * lda + (size_t)h * DH;
        Bp += (size_t)(b * SS) * ldb + (size_t)h * DH;
        Cp += (size_t)z * SS * SS;
    } else {
        int e = z >> 2, part = z & 3;
        Ap += (size_t)e * sA + (size_t)part * K;
        Bp += (size_t)e * sB + (size_t)part * K * ldb;
        Cp += (size_t)part * PSPLIT + (size_t)e * sC;
    }

    int m0 = blockIdx.y * TM, n0 = blockIdx.x * TN;
    if (TRI == 1 && n0 >= m0 + TM) return;

    int tid = threadIdx.x;
    constexpr int KS = 16;
    constexpr int TX = TN / 8;
    int ty = tid / TX, tx = tid % TX;

    __shared__ float As[2][KS][TM + 4];
    __shared__ float Bs[2][KS][TN + 4];

    constexpr int APF = (TA == 0) ? (TM * KS / 256) : 1;
    constexpr int BPF = (TB == 1) ? (TN * KS / 256) : 1;
    float4 pa[APF], pb[BPF];

    auto loadA = [&](int k0) {            // TA==0: reg prefetch row-major
        #pragma unroll
        for (int r = 0; r < TM * KS / 256; r++) {
            int idx = tid + r * 64;
            int row = idx >> 2, kh = (idx & 3) * 4;
            pa[r] = *(const float4*)(Ap + (size_t)(m0 + row) * lda + k0 + kh);
        }
    };
    auto storeA = [&](int buf) {
        #pragma unroll
        for (int r = 0; r < TM * KS / 256; r++) {
            int idx = tid + r * 64;
            int row = idx >> 2, kh = (idx & 3) * 4;
            As[buf][kh + 0][row] = pa[r].x; As[buf][kh + 1][row] = pa[r].y;
            As[buf][kh + 2][row] = pa[r].z; As[buf][kh + 3][row] = pa[r].w;
        }
    };
    auto asyncA = [&](int k0, int buf) {  // TA==1: K-major, direct async
        #pragma unroll
        for (int r = 0; r < TM * KS / 256; r++) {
            int idx = tid + r * 64;
            int k = idx / (TM / 4), m4 = (idx % (TM / 4)) * 4;
            cp16(&As[buf][k][m4], Ap + (size_t)(k0 + k) * lda + m0 + m4);
        }
    };
    auto asyncB = [&](int k0, int buf) {  // TB==0: row-major, direct async
        #pragma unroll
        for (int r = 0; r < TN * KS / 256; r++) {
            int idx = tid + r * 64;
            int k = idx / (TN / 4), n4 = (idx % (TN / 4)) * 4;
            cp16(&Bs[buf][k][n4], Bp + (size_t)(k0 + k) * ldb + n0 + n4);
        }
    };
    auto loadB = [&](int k0) {            // TB==1: reg prefetch N-major
        #pragma unroll
        for (int r = 0; r < TN * KS / 256; r++) {
            int idx = tid + r * 64;
            int n = idx >> 2, kh = (idx & 3) * 4;
            pb[r] = *(const float4*)(Bp + (size_t)(n0 + n) * ldb + k0 + kh);
        }
    };
    auto storeB = [&](int buf) {
        #pragma unroll
        for (int r = 0; r < TN * KS / 256; r++) {
            int idx = tid + r * 64;
            int n = idx >> 2, kh = (idx & 3) * 4;
            Bs[buf][kh + 0][n] = pb[r].x; Bs[buf][kh + 1][n] = pb[r].y;
            Bs[buf][kh + 2][n] = pb[r].z; Bs[buf][kh + 3][n] = pb[r].w;
        }
    };

    unsigned long long acc[8][4];
    #pragma unroll
    for (int i = 0; i < 8; i++)
        #pragma unroll
        for (int j = 0; j < 4; j++) acc[i][j] = 0ull;

    int kbeg = (TRI == 2) ? m0 : 0;
    int nk = (K - kbeg) / KS;

    if (TA == 0) loadA(kbeg); else asyncA(kbeg, 0);
    if (TB == 1) loadB(kbeg); else asyncB(kbeg, 0);
    if (TA == 0) storeA(0);
    if (TB == 1) storeB(0);
    if (TA == 1 || TB == 0) { cp_commit(); cp_wait0(); }
    __syncthreads();

    for (int t = 0; t < nk; t++) {
        int cur = t & 1;
        bool has = (t + 1 < nk);
        if (has) {
            int kn = kbeg + (t + 1) * KS;
            if (TA == 0) loadA(kn); else asyncA(kn, cur ^ 1);
            if (TB == 1) loadB(kn); else asyncB(kn, cur ^ 1);
            if (TA == 1 || TB == 0) cp_commit();
        }
        #pragma unroll
        for (int k = 0; k < KS; k++) {
            float4 a0 = *(const float4*)&As[cur][k][ty * 8];
            float4 a1 = *(const float4*)&As[cur][k][ty * 8 + 4];
            float4 b0 = *(const float4*)&Bs[cur][k][tx * 8];
            float4 b1 = *(const float4*)&Bs[cur][k][tx * 8 + 4];
            unsigned long long bp[4] = {pk2(b0.x, b0.y), pk2(b0.z, b0.w),
                                        pk2(b1.x, b1.y), pk2(b1.z, b1.w)};
            float av[8] = {a0.x, a0.y, a0.z, a0.w, a1.x, a1.y, a1.z, a1.w};
            #pragma unroll
            for (int i = 0; i < 8; i++) {
                unsigned long long ap = pk2(av[i], av[i]);
                #pragma unroll
                for (int j = 0; j < 4; j++) fma2(acc[i][j], ap, bp[j]);
            }
        }
        if (has) {
            if (TA == 0) storeA(cur ^ 1);
            if (TB == 1) storeB(cur ^ 1);
        }
        if (TA == 1 || TB == 0) cp_wait0();
        __syncthreads();
    }

    #pragma unroll
    for (int i = 0; i < 8; i++) {
        int m = m0 + ty * 8 + i;
        float4 v0, v1;
        upk2(acc[i][0], v0.x, v0.y); upk2(acc[i][1], v0.z, v0.w);
        upk2(acc[i][2], v1.x, v1.y); upk2(acc[i][3], v1.z, v1.w);
        if (RELU) {
            v0.x = fmaxf(v0.x, 0.f); v0.y = fmaxf(v0.y, 0.f);
            v0.z = fmaxf(v0.z, 0.f); v0.w = fmaxf(v0.w, 0.f);
            v1.x = fmaxf(v1.x, 0.f); v1.y = fmaxf(v1.y, 0.f);
            v1.z = fmaxf(v1.z, 0.f); v1.w = fmaxf(v1.w, 0.f);
        }
        *(float4*)(Cp + (size_t)m * ldc + n0 + tx * 8) = v0;
        *(float4*)(Cp + (size_t)m * ldc + n0 + tx * 8 + 4) = v1;
    }
}

// ---------------- split-K small-N GEMM (router, gate) ----------------
template<int N>
__global__ __launch_bounds__(256) void smallgemm_part(const float* __restrict__ A,
                                                      const float* __restrict__ B,
                                                      float* __restrict__ Cp)
{
    __shared__ float As[32][68];
    __shared__ float Bs[64 * N];
    int tid = threadIdx.x;
    int n0 = blockIdx.x * 32;
    int kc0 = blockIdx.y * (DM / KSP);
    constexpr int OPT = N / 8;
    int t = tid >> 3, j0 = (tid & 7) * OPT;
    float acc[OPT] = {};

    for (int kc = kc0; kc < kc0 + DM / KSP; kc += 64) {
        __syncthreads();
        for (int i = tid; i < 32 * 16; i += 256) {
            int tok = i >> 4, q = (i & 15) * 4;
            *(float4*)&As[tok][q] = *(const float4*)(A + (size_t)(n0 + tok) * DM + kc + q);
        }
        const float4* Bg = (const float4*)(B + (size_t)kc * N);
        float4* Bs4 = (float4*)Bs;
        for (int i = tid; i < 16 * N; i += 256) Bs4[i] = Bg[i];
        __syncthreads();
        #pragma unroll 8
        for (int k = 0; k < 64; k++) {
            float a = As[t][k];
            #pragma unroll
            for (int j = 0; j < OPT; j++) acc[j] += a * Bs[k * N + j0 + j];
        }
    }
    float* out = Cp + (size_t)blockIdx.y * NTOK * N;
    #pragma unroll
    for (int j = 0; j < OPT; j++)
        out[(size_t)(n0 + t) * N + j0 + j] = acc[j];
}

// ---------------- expert V/O projections ----------------
#define PROJ_SMEM ((4*DH*DH + 32*68) * 4)
template<int OPROJ>
__global__ __launch_bounds__(256) void proj_kernel(const float* __restrict__ W,
                                                   const float* __restrict__ xres)
{
    extern __shared__ float sm[];
    float* sW = sm;
    float* sx = sm + 4 * DH * DH;
    int h = blockIdx.y, n0 = blockIdx.x * 32;
    int tid = threadIdx.x;

    const float4* Wg = (const float4*)(W + (size_t)h * EA * DH * DH);
    float4* sW4 = (float4*)sW;
    #pragma unroll
    for (int i = 0; i < 16; i++) sW4[tid + i * 256] = Wg[tid + i * 256];

    for (int i = tid; i < 32 * DH; i += 256) {
        int tok = i >> 6, d = i & 63;
        float v;
        if (OPROJ) v = g_ao[((size_t)h * NTOK + n0 + tok) * DH + d];
        else       v = g_xln1[(size_t)(n0 + tok) * DM + h * DH + d];
        sx[tok * 68 + d] = v;
    }
    __syncthreads();

    int t = tid >> 3;
    int e0 = (tid & 7) * 8;
    int n = n0 + t;
    int a = g_idx[n * HH + h];
    const float* Wt = sW + a * DH * DH;
    float acc[8] = {};
    #pragma unroll 8
    for (int d = 0; d < DH; d++) {
        float xv = sx[t * 68 + d];
        float4 w0 = *(const float4*)&Wt[d * DH + e0];
        float4 w1 = *(const float4*)&Wt[d * DH + e0 + 4];
        acc[0] += xv * w0.x; acc[1] += xv * w0.y;
        acc[2] += xv * w0.z; acc[3] += xv * w0.w;
        acc[4] += xv * w1.x; acc[5] += xv * w1.y;
        acc[6] += xv * w1.z; acc[7] += xv * w1.w;
    }
    if (OPROJ) {
        size_t off = (size_t)n * DM + h * DH + e0;
        float4 r0 = *(const float4*)(xres + off);
        float4 r1 = *(const float4*)(xres + off + 4);
        float4 v0 = make_float4(r0.x + acc[0], r0.y + acc[1], r0.z + acc[2], r0.w + acc[3]);
        float4 v1 = make_float4(r1.x + acc[4], r1.y + acc[5], r1.z + acc[6], r1.w + acc[7]);
        *(float4*)(g_x1 + off) = v0;
        *(float4*)(g_x1 + off + 4) = v1;
    } else {
        size_t off = ((size_t)h * NTOK + n) * DH + e0;
        *(float4*)(g_vproj + off) = make_float4(acc[0], acc[1], acc[2], acc[3]);
        *(float4*)(g_vproj + off + 4) = make_float4(acc[4], acc[5], acc[6], acc[7]);
    }
}

// ---------------- routing ----------------
__global__ void init_hard_kernel()
{
    if (threadIdx.x < HH * EA) g_hard[threadIdx.x] = 0;
}

__global__ void argmax_kernel()
{
    int i = blockIdx.x * blockDim.x + threadIdx.x;
    if (i >= NTOK * HH) return;
    int n = i / HH, h = i % HH;
    float v[EA];
    #pragma unroll
    for (int a = 0; a < EA; a++) {
        float s = 0.f;
        #pragma unroll
        for (int ks = 0; ks < KSP; ks++)
            s += g_rp[(size_t)ks * NTOK * HH * EA + (size_t)n * HH * EA + h * EA + a];
        v[a] = s;
    }
    int best = 0; float bv = v[0];
    #pragma unroll
    for (int a = 1; a < EA; a++) if (v[a] > bv) { bv = v[a]; best = a; }
    g_idx[i] = best;
    atomicAdd(&g_hard[h * EA + best], 1);
}

__global__ void aux1_kernel()
{
    if (threadIdx.x != 0) return;
    float e[HH * EA];
    float tot = 0.f;
    for (int i = 0; i < HH * EA; i++) { e[i] = 0.01f * (float)g_hard[i] / (float)NTOK; tot += e[i]; }
    float a = 0.f;
    for (int i = 0; i < HH * EA; i++) { float pr = e[i] / (tot + 1e-9f); a += pr * pr; }
    g_aux[0] = a * (float)(EA * HH);
}

// parallel top-2 over summed gate partials
__global__ __launch_bounds__(256) void topk_kernel()
{
    int n = blockIdx.x * 256 + threadIdx.x;
    if (n >= NTOK) return;
    float g[EF];
    #pragma unroll
    for (int j = 0; j < EF; j++) {
        float s = 0.f;
        #pragma unroll
        for (int ks = 0; ks < KSP; ks++)
            s += g_glp[(size_t)ks * NTOK * EF + (size_t)n * EF + j];
        g[j] = s;
    }
    int i0 = 0; float v0 = g[0];
    #pragma unroll
    for (int j = 1; j < EF; j++) if (g[j] > v0) { v0 = g[j]; i0 = j; }
    int i1 = -1; float v1 = -1e30f;
    #pragma unroll
    for (int j = 0; j < EF; j++) { if (j == i0) continue; if (g[j] > v1) { v1 = g[j]; i1 = j; } }
    float e1 = expf(v1 - v0);
    float den = 1.f + e1;
    g_tei[2 * n] = i0; g_tei[2 * n + 1] = i1;
    g_tpw[2 * n] = 1.f / den; g_tpw[2 * n + 1] = e1 / den;
}

// single-block: capacity scan + weights + aux2
__global__ __launch_bounds__(256) void route_scan_kernel()
{
    int tid = threadIdx.x;
    __shared__ int   s_e[NE];
    __shared__ float s_p[NE];
    __shared__ int   s_pos[NE];
    __shared__ int   s_keep[NE];
    __shared__ float s_imp[EF];
    __shared__ int   s_cnt[EF];

    for (int j = tid; j < NE; j += 256) { s_e[j] = g_tei[j]; s_p[j] = g_tpw[j]; }
    __syncthreads();
    if (tid == 0) {
        int cnt[EF] = {};
        for (int j = 0; j < NE; j++) {
            int e = s_e[j];
            int p = cnt[e]++;
            s_pos[j] = p;
            s_keep[j] = (p < CAP) ? 1 : 0;
        }
    }
    __syncthreads();
    if (tid < EF) { s_imp[tid] = 0.f; s_cnt[tid] = 0; }
    __syncthreads();
    for (int n = tid; n < NTOK; n += 256) {
        float p0 = s_p[2 * n]     * (float)s_keep[2 * n];
        float p1 = s_p[2 * n + 1] * (float)s_keep[2 * n + 1];
        float den = p0 + p1 + 1e-9f;
        float w0 = p0 / den, w1 = p1 / den;
        g_ew[2 * n] = w0;      g_ew[2 * n + 1] = w1;
        g_ee[2 * n] = s_e[2 * n];       g_ee[2 * n + 1] = s_e[2 * n + 1];
        g_epos[2 * n] = s_pos[2 * n];   g_epos[2 * n + 1] = s_pos[2 * n + 1];
        g_ekeep[2 * n] = s_keep[2 * n]; g_ekeep[2 * n + 1] = s_keep[2 * n + 1];
        if (s_keep[2 * n])     { atomicAdd(&s_cnt[s_e[2 * n]], 1);     atomicAdd(&s_imp[s_e[2 * n]], w0); }
        if (s_keep[2 * n + 1]) { atomicAdd(&s_cnt[s_e[2 * n + 1]], 1); atomicAdd(&s_imp[s_e[2 * n + 1]], w1); }
    }
    __syncthreads();
    if (tid == 0) {
        float ct = 0.f, it = 0.f;
        for (int e = 0; e < EF; e++) { ct += (float)s_cnt[e]; it += s_imp[e]; }
        float a = 0.f;
        for (int e = 0; e < EF; e++)
            a += ((float)s_cnt[e] / (ct + 1e-9f)) * (s_imp[e] / (it + 1e-9f));
        g_aux[1] = a * (float)EF;
    }
}

__global__ __launch_bounds__(256) void softmax_kernel(const float* __restrict__ mask)
{
    int row = blockIdx.x;
    int tid = threadIdx.x;
    int s = row & (SS - 1);
    float* p = g_p + (size_t)row * SS;
    const float* mr = mask + (size_t)s * SS;

    float m0v = mr[tid], m1v = mr[tid + 256];
    float v0 = p[tid] * 0.125f + m0v;
    float v1 = p[tid + 256] * 0.125f + m1v;

    __shared__ float red[8];
    int lane = tid & 31, w = tid >> 5;

    float mx = fmaxf(v0, v1);
    #pragma unroll
    for (int o = 16; o; o >>= 1) mx = fmaxf(mx, __shfl_xor_sync(~0u, mx, o));
    if (lane == 0) red[w] = mx;
    __syncthreads();
    if (w == 0) {
        float m = (lane < 8) ? red[lane] : -1e30f;
        #pragma unroll
        for (int o = 4; o; o >>= 1) m = fmaxf(m, __shfl_xor_sync(~0u, m, o));
        if (lane == 0) red[0] = m;
    }
    __syncthreads();
    mx = red[0];
    __syncthreads();

    float e0 = (m0v < -1e8f) ? 0.f : expf(v0 - mx);
    float e1 = (m1v < -1e8f) ? 0.f : expf(v1 - mx);
    float sm = e0 + e1;
    #pragma unroll
    for (int o = 16; o; o >>= 1) sm += __shfl_xor_sync(~0u, sm, o);
    if (lane == 0) red[w] = sm;
    __syncthreads();
    if (w == 0) {
        float m = (lane < 8) ? red[lane] : 0.f;
        #pragma unroll
        for (int o = 4; o; o >>= 1) m += __shfl_xor_sync(~0u, m, o);
        if (lane == 0) red[0] = m;
    }
    __syncthreads();
    float inv = 1.f / red[0];
    p[tid] = e0 * inv;
    p[tid + 256] = e1 * inv;
}

__global__ __launch_bounds__(192) void scatter_kernel()
{
    int j = blockIdx.x;
    if (!g_ekeep[j]) return;
    int tok = j >> 1;
    float4* dst = (float4*)(g_buf + ((size_t)g_ee[j] * CAP + g_epos[j]) * DM);
    const float4* src = (const float4*)(g_xln2 + (size_t)tok * DM);
    for (int d = threadIdx.x; d < DM / 4; d += 192) dst[d] = src[d];
}

__global__ __launch_bounds__(256) void output_kernel(float* __restrict__ out, int out_size)
{
    int n = blockIdx.x, tid = threadIdx.x;
    float w0 = g_ew[2 * n], w1 = g_ew[2 * n + 1];
    size_t o0 = ((size_t)g_ee[2 * n]     * CAP + g_epos[2 * n])     * DM;
    size_t o1 = ((size_t)g_ee[2 * n + 1] * CAP + g_epos[2 * n + 1]) * DM;
    bool k0 = g_ekeep[2 * n] != 0, k1 = g_ekeep[2 * n + 1] != 0;
    for (int d = tid; d < DM; d += 256) {
        float f = 0.f;
        if (k0) f += w0 * (g_ybuf[o0 + d] + g_ybuf[PSPLIT + o0 + d]
                         + g_ybuf[2 * PSPLIT + o0 + d] + g_ybuf[3 * PSPLIT + o0 + d]);
        if (k1) f += w1 * (g_ybuf[o1 + d] + g_ybuf[PSPLIT + o1 + d]
                         + g_ybuf[2 * PSPLIT + o1 + d] + g_ybuf[3 * PSPLIT + o1 + d]);
        out[(size_t)n * DM + d] = g_x1[(size_t)n * DM + d] + f;
    }
    if (n == 0 && tid == 0 && out_size > NTOK * DM)
        out[NTOK * DM] = g_aux[0] + g_aux[1];
}

// ---------------- host launcher ----------------
extern "C" void kernel_launch(void* const* d_in, const int* in_sizes, int n_in,
                              void* d_out, int out_size)
{
    const float* x        = (const float*)d_in[0];
    const float* mask     = (const float*)d_in[1];
    const float* ln1_g    = (const float*)d_in[2];
    const float* ln1_b    = (const float*)d_in[3];
    const float* ln2_g    = (const float*)d_in[4];
    const float* ln2_b    = (const float*)d_in[5];
    const float* W_q      = (const float*)d_in[6];
    const float* W_k      = (const float*)d_in[7];
    const float* W_v      = (const float*)d_in[8];
    const float* W_o      = (const float*)d_in[9];
    const float* router_w = (const float*)d_in[10];
    const float* gate_w   = (const float*)d_in[11];
    const float* W1       = (const float*)d_in[12];
    const float* W2       = (const float*)d_in[13];
    float* out = (float*)d_out;

    float *p_xln1, *p_qk, *p_rp, *p_p, *p_vproj, *p_ao, *p_x1, *p_xln2,
          *p_glp, *p_buf, *p_hmid, *p_ybuf;
    cudaGetSymbolAddress((void**)&p_xln1,  g_xln1);
    cudaGetSymbolAddress((void**)&p_qk,    g_qk);
    cudaGetSymbolAddress((void**)&p_rp,    g_rp);
    cudaGetSymbolAddress((void**)&p_p,     g_p);
    cudaGetSymbolAddress((void**)&p_vproj, g_vproj);
    cudaGetSymbolAddress((void**)&p_ao,    g_ao);
    cudaGetSymbolAddress((void**)&p_x1,    g_x1);
    cudaGetSymbolAddress((void**)&p_xln2,  g_xln2);
    cudaGetSymbolAddress((void**)&p_glp,   g_glp);
    cudaGetSymbolAddress((void**)&p_buf,   g_buf);
    cudaGetSymbolAddress((void**)&p_hmid,  g_hmid);
    cudaGetSymbolAddress((void**)&p_ybuf,  g_ybuf);
    float* p_q = p_qk;
    float* p_k = p_qk + (size_t)NTOK * DM;

    static int smem_set = 0;
    if (!smem_set) {
        cudaFuncSetAttribute(proj_kernel<0>, cudaFuncAttributeMaxDynamicSharedMemorySize, PROJ_SMEM);
        cudaFuncSetAttribute(proj_kernel<1>, cudaFuncAttributeMaxDynamicSharedMemorySize, PROJ_SMEM);
        smem_set = 1;
    }

    init_hard_kernel<<<1, 64>>>();
    ln_kernel<<<NTOK, 256>>>(x, ln1_g, ln1_b, p_xln1);

    gemm_t<64,64,0,0,0,1,0><<<dim3(12, 16, 2), 64>>>(p_xln1, W_q, W_k, p_qk,
        NTOK, DM, DM, DM, DM, DM, 0, 0, (size_t)NTOK*DM);

    smallgemm_part<HH*EA><<<dim3(NTOK/32, KSP), 256>>>(p_xln1, router_w, p_rp);

    argmax_kernel<<<(NTOK*HH + 255)/256, 256>>>();
    aux1_kernel<<<1, 32>>>();

    proj_kernel<0><<<dim3(NTOK/32, HH), 256, PROJ_SMEM>>>(W_v, nullptr);

    gemm_t<64,64,0,1,0,2,1><<<dim3(8, 8, HH*BB), 64>>>(p_q, p_k, nullptr, p_p,
        SS, SS, DH, DM, DM, SS, 0, 0, 0);
    softmax_kernel<<<HH*BB*SS, 256>>>(mask);

    gemm_t<64,64,1,0,0,0,2><<<dim3(1, 8, HH*BB), 64>>>(p_p, p_vproj, nullptr, p_ao,
        SS, DH, SS, SS, DH, DH, (size_t)SS*SS, (size_t)SS*DH, (size_t)SS*DH);

    proj_kernel<1><<<dim3(NTOK/32, HH), 256, PROJ_SMEM>>>(W_o, x);

    ln_kernel<<<NTOK, 256>>>(p_x1, ln2_g, ln2_b, p_xln2);
    smallgemm_part<EF><<<dim3(NTOK/32, KSP), 256>>>(p_xln2, gate_w, p_glp);

    topk_kernel<<<NTOK/256, 256>>>();
    route_scan_kernel<<<1, 256>>>();
    scatter_kernel<<<NE, 192>>>();

    gemm_t<32,128,0,0,1,0,0><<<dim3(24, 5, EF), 64>>>(p_buf, W1, nullptr, p_hmid,
        CAP, DFF, DM, DM, DFF, DFF, (size_t)CAP*DM, (size_t)DM*DFF, (size_t)CAP*DFF);

    gemm_t<32,128,0,0,0,3,0><<<dim3(6, 5, EF*4), 64>>>(p_hmid, W2, nullptr, p_ybuf,
        CAP, DM, DFF/4, DFF, DM, DM, (size_t)CAP*DFF, (size_t)DFF*DM, (size_t)CAP*DM);

    output_kernel<<<NTOK, 256>>>(out, out_size);
}